// round 3
// baseline (speedup 1.0000x reference)
#include <cuda_runtime.h>
#include <math.h>

#define BB 4
#define TT 192
#define LL 120
#define GG 500
#define HH 500      // HL
#define H4 2000
#define NR 480      // B*L
#define OD 24
#define M1 3000
#define M2 1000

#define KSLAB 100
#define SMEM_STEP ((KSLAB*128 + KSLAB*64)*4)

// ------------------------- scratch (device globals) -------------------------
__device__ float g_P[GG];
__device__ float g_Nv[GG];
__device__ float g_rho[GG];     // sorted breakpoints
__device__ float g_esign[GG];
__device__ int   g_ef[GG];
__device__ int   g_act0[GG];
__device__ int   g_nev[1];
__device__ float g_bias[H4];               // interleaved hc*4+gate
__device__ float g_Aseg[(GG + 1) * H4];    // interleaved
__device__ float g_Bseg[(GG + 1) * H4];    // interleaved
__device__ float g_WihT[GG * H4];   // [f][h]  (h in ORIGINAL gate*500+hc order)
__device__ float g_WX[HH * H4];     // [k][hc*4+gate]
__device__ float g_u[TT * NR];
__device__ float g_v[TT * NR];
__device__ int   g_seg[TT * NR];
__device__ float g_hA[HH * NR];     // h, k-major: [hcol][n]
__device__ float g_hB[HH * NR];
__device__ float g_c[HH * NR];      // c, k-major
__device__ float g_hT[NR * HH];     // h_last row-major for MLP
__device__ float g_z1[NR * M1];
__device__ float g_z2[NR * M2];
__device__ float g_z3[NR * M1];

// ------------------------- math helpers -------------------------
__device__ __forceinline__ float fsig(float x) {
    return __fdividef(1.f, 1.f + __expf(-x));
}
__device__ __forceinline__ float ftanh(float x) {
    float ax = fabsf(x);
    float t  = __expf(-2.f * ax);
    float r  = __fdividef(1.f - t, 1.f + t);
    return copysignf(r, x);
}

// packed fp32x2 fma (SASS FFMA2) — lane-wise IEEE fp32, bit-identical to fmaf
#define FMA2(d, a, b) asm("fma.rn.f32x2 %0, %1, %2, %0;" : "+l"(d) : "l"(a), "l"(b))

// ------------------------- P,N precompute -------------------------
__global__ void k_prep_pn(const float* __restrict__ W1, const float* __restrict__ W2) {
    int f = threadIdx.x;
    if (f >= GG) return;
    float p = 0.f, n = 0.f;
    for (int g = 0; g < GG; g++) {
        float w = W1[g];
        float v = W2[g * GG + f];
        p = fmaf(fmaxf(w, 0.f), v, p);
        n = fmaf(fmaxf(-w, 0.f), v, n);
    }
    g_P[f]  = p;
    g_Nv[f] = n;
}

// ------------------------- relu breakpoint events + sort -------------------------
__global__ void k_events() {
    __shared__ float srho[GG];
    __shared__ float ssg[GG];
    __shared__ int   sf[GG];
    __shared__ int   cnt;
    int tid = threadIdx.x;
    if (tid == 0) cnt = 0;
    __syncthreads();
    if (tid < GG) {
        float p = g_P[tid], n = g_Nv[tid];
        int act0 = 0;
        float sgn = 0.f, rho = 0.f;
        if (n > 0.f) {
            if (p >= 0.f) { act0 = 1; }
            else { act0 = 0; rho = __fdividef(-p, n); sgn = 1.f; }
        } else if (n < 0.f) {
            if (p > 0.f) { act0 = 1; rho = __fdividef(p, -n); sgn = -1.f; }
            else { act0 = 0; }
        } else {
            act0 = (p > 0.f) ? 1 : 0;
        }
        g_act0[tid] = act0;
        if (sgn != 0.f) {
            int e = atomicAdd(&cnt, 1);
            srho[e] = rho; ssg[e] = sgn; sf[e] = tid;
        }
    }
    __syncthreads();
    int E = cnt;
    if (tid == 0) g_nev[0] = E;
    if (tid < E) {
        float r = srho[tid];
        int rank = 0;
        for (int j = 0; j < E; j++) {
            float rj = srho[j];
            rank += (rj < r) || (rj == r && j < tid);
        }
        g_rho[rank]   = r;
        g_esign[rank] = ssg[tid];
        g_ef[rank]    = sf[tid];
    }
}

// ------------------------- tiled transposes -------------------------
// g_WihT[f][h] = W_ih[h][f];  in: [2000][500]
__global__ void k_wihT(const float* __restrict__ W_ih) {
    __shared__ float tle[32][33];
    int f0 = blockIdx.x * 32;   // 16 tiles over 500
    int h0 = blockIdx.y * 32;   // 63 tiles over 2000
    int x = threadIdx.x, y = threadIdx.y;
    for (int i = y; i < 32; i += 8) {
        int h = h0 + i, f = f0 + x;
        tle[i][x] = (h < H4 && f < GG) ? W_ih[h * GG + f] : 0.f;
    }
    __syncthreads();
    for (int i = y; i < 32; i += 8) {
        int f = f0 + i, h = h0 + x;
        if (f < GG && h < H4) g_WihT[f * H4 + h] = tle[x][i];
    }
}

// g_WX[k][hc*4+g] = W_hh[g*HH+hc][k];  in: [2000][500]
__global__ void k_wx2(const float* __restrict__ W_hh) {
    __shared__ float tle[32][33];
    int k0 = blockIdx.x * 32;   // 16 tiles over 500
    int r0 = blockIdx.y * 32;   // 63 tiles over 2000
    int x = threadIdx.x, y = threadIdx.y;
    for (int i = y; i < 32; i += 8) {
        int r = r0 + i, k = k0 + x;
        tle[i][x] = (r < H4 && k < HH) ? W_hh[r * HH + k] : 0.f;
    }
    __syncthreads();
    for (int i = y; i < 32; i += 8) {
        int k = k0 + i, r = r0 + x;
        if (k < HH && r < H4) {
            int g = r / HH, hc = r % HH;
            g_WX[k * H4 + hc * 4 + g] = tle[x][i];
        }
    }
}

__global__ void k_bias(const float* __restrict__ b_ih, const float* __restrict__ b_hh) {
    int h = blockIdx.x * 256 + threadIdx.x;
    if (h >= H4) return;
    int q = (h % HH) * 4 + (h / HH);
    g_bias[q] = b_ih[h] + b_hh[h];
}

// ------------------------- segment prefix tables (interleaved cols) ---------
__global__ void k_tables() {
    int h = blockIdx.x * 256 + threadIdx.x;  // ORIGINAL index gate*HH+hc
    if (h >= H4) return;
    int q = (h % HH) * 4 + (h / HH);         // interleaved position
    float accA = 0.f, accB = 0.f;
    for (int f = 0; f < GG; f++) {
        if (g_act0[f]) {
            float w = g_WihT[f * H4 + h];
            accA = fmaf(w, g_P[f],  accA);
            accB = fmaf(w, g_Nv[f], accB);
        }
    }
    g_Aseg[q] = accA;
    g_Bseg[q] = accB;
    int E = g_nev[0];
    for (int e = 0; e < E; e++) {
        int f = g_ef[e];
        float sgn = g_esign[e];
        float w = g_WihT[f * H4 + h] * sgn;
        accA = fmaf(w, g_P[f],  accA);
        accB = fmaf(w, g_Nv[f], accB);
        g_Aseg[(e + 1) * H4 + q] = accA;
        g_Bseg[(e + 1) * H4 + q] = accB;
    }
}

// ------------------------- GCN front: u, v per (b,t,l) -------------------------
__global__ void k_front(const float* __restrict__ x, const float* __restrict__ Ahat) {
    __shared__ float xr[LL], sp[LL], sn[LL];
    int bid = blockIdx.x;           // b*TT + t
    int b = bid / TT, t = bid % TT;
    int tid = threadIdx.x;
    if (tid < LL) xr[tid] = x[(b * TT + t) * LL + tid];
    __syncthreads();
    if (tid < LL) {
        float s = 0.f;
        const float* Ar = &Ahat[tid * LL];
        for (int l = 0; l < LL; l++) s = fmaf(Ar[l], xr[l], s);
        sp[tid] = fmaxf(s, 0.f);
        sn[tid] = fmaxf(-s, 0.f);
    }
    __syncthreads();
    if (tid < LL) {
        float uu = 0.f, vv = 0.f;
        const float* Ar = &Ahat[tid * LL];
        for (int l = 0; l < LL; l++) {
            uu = fmaf(Ar[l], sp[l], uu);
            vv = fmaf(Ar[l], sn[l], vv);
        }
        int n = b * LL + tid;
        g_u[t * NR + n] = uu;
        g_v[t * NR + n] = vv;
    }
}

// ------------------------- segment lookup per point -------------------------
__global__ void k_seg() {
    int idx = blockIdx.x * 256 + threadIdx.x;
    if (idx >= TT * NR) return;
    float uu = g_u[idx], vv = g_v[idx];
    int E = g_nev[0];
    int s;
    if (uu > 0.f) {
        float rho = vv / uu;
        int lo = 0, hi = E;
        while (lo < hi) {
            int mid = (lo + hi) >> 1;
            if (g_rho[mid] < rho) lo = mid + 1; else hi = mid;
        }
        s = lo;
    } else {
        s = (vv > 0.f) ? E : 0;
    }
    g_seg[idx] = s;
}

// ------------------------- init h,c -------------------------
__global__ void k_init() {
    int idx = blockIdx.x * 256 + threadIdx.x;
    if (idx < HH * NR) g_hA[idx] = 0.f;
    else if (idx < 2 * HH * NR) g_c[idx - HH * NR] = 0.f;
}

// ------------------------- fused LSTM step (FFMA2 packed) -------------------------
// grid (16,15): 32 hcols (128 gate-cols) x 32 rows per block. 128 threads:
// cx=tid&15 -> 8 cols (2 hcol quads), ry=tid>>4 -> 4 rows. f32x2 packed over col pairs.
__global__ __launch_bounds__(128) void k_step2(int t, int parity) {
    extern __shared__ float sm[];
    float* sW = sm;                    // [KSLAB][128]  natural col pairs
    float* sH = sm + KSLAB * 128;      // [KSLAB][64]   rows duplicated (h,h)
    const float* hin = parity ? g_hB : g_hA;
    float*      hout = parity ? g_hA : g_hB;
    int tid = threadIdx.x;
    int cx = tid & 15;
    int ry = tid >> 4;
    int hc0 = blockIdx.x * 32;
    int n0  = blockIdx.y * 32;
    int c0 = cx * 8;
    int nb = n0 + ry * 4;
    int gbase = hc0 * 4 + c0;
    bool colv = (gbase + 7 < H4);
    int gb = colv ? gbase : 0;

    unsigned long long acc[4][4];
    // prologue: gates_x = u*Aseg[s] + v*Bseg[s] + bias (interleaved layout)
    #pragma unroll
    for (int r = 0; r < 4; r++) {
        int pidx = t * NR + nb + r;
        float uu = g_u[pidx], vv = g_v[pidx];
        int s = g_seg[pidx];
        const float4* Ar = (const float4*)&g_Aseg[s * H4 + gb];
        const float4* Br = (const float4*)&g_Bseg[s * H4 + gb];
        const float4* Bi = (const float4*)&g_bias[gb];
        #pragma unroll
        for (int q = 0; q < 2; q++) {
            float4 a4 = Ar[q], b4 = Br[q], c4 = Bi[q];
            float2 p0 = make_float2(fmaf(uu, a4.x, fmaf(vv, b4.x, c4.x)),
                                    fmaf(uu, a4.y, fmaf(vv, b4.y, c4.y)));
            float2 p1 = make_float2(fmaf(uu, a4.z, fmaf(vv, b4.z, c4.z)),
                                    fmaf(uu, a4.w, fmaf(vv, b4.w, c4.w)));
            acc[r][q * 2]     = *(unsigned long long*)&p0;
            acc[r][q * 2 + 1] = *(unsigned long long*)&p1;
        }
    }

    for (int k0 = 0; k0 < HH; k0 += KSLAB) {
        #pragma unroll 1
        for (int e = tid; e < KSLAB * 32; e += 128) {
            int kk = e >> 5, j4 = (e & 31) * 4;
            int col = hc0 * 4 + j4;
            float4 v = make_float4(0.f, 0.f, 0.f, 0.f);
            if (col + 3 < H4) v = *(const float4*)&g_WX[(k0 + kk) * H4 + col];
            *(float4*)&sW[kk * 128 + j4] = v;
        }
        #pragma unroll 1
        for (int e = tid; e < KSLAB * 32; e += 128) {
            int kk = e >> 5, nn = e & 31;
            float val = hin[(k0 + kk) * NR + n0 + nn];
            *(float2*)&sH[kk * 64 + nn * 2] = make_float2(val, val);
        }
        __syncthreads();
        #pragma unroll 4
        for (int kk = 0; kk < KSLAB; kk++) {
            ulonglong2 w01 = *(const ulonglong2*)&sW[kk * 128 + c0];
            ulonglong2 w23 = *(const ulonglong2*)&sW[kk * 128 + c0 + 4];
            ulonglong2 hA  = *(const ulonglong2*)&sH[kk * 64 + ry * 8];
            ulonglong2 hB  = *(const ulonglong2*)&sH[kk * 64 + ry * 8 + 4];
            FMA2(acc[0][0], hA.x, w01.x); FMA2(acc[0][1], hA.x, w01.y);
            FMA2(acc[0][2], hA.x, w23.x); FMA2(acc[0][3], hA.x, w23.y);
            FMA2(acc[1][0], hA.y, w01.x); FMA2(acc[1][1], hA.y, w01.y);
            FMA2(acc[1][2], hA.y, w23.x); FMA2(acc[1][3], hA.y, w23.y);
            FMA2(acc[2][0], hB.x, w01.x); FMA2(acc[2][1], hB.x, w01.y);
            FMA2(acc[2][2], hB.x, w23.x); FMA2(acc[2][3], hB.x, w23.y);
            FMA2(acc[3][0], hB.y, w01.x); FMA2(acc[3][1], hB.y, w01.y);
            FMA2(acc[3][2], hB.y, w23.x); FMA2(acc[3][3], hB.y, w23.y);
        }
        __syncthreads();
    }

    // epilogue: 2 hcols x 4 rows per thread; cols within quad = (i,f,g,o)
    #pragma unroll
    for (int u2 = 0; u2 < 2; u2++) {
        int hc = hc0 + 2 * cx + u2;
        if (hc >= HH) continue;
        float4 cold = *(float4*)&g_c[hc * NR + nb];
        float cc[4] = {cold.x, cold.y, cold.z, cold.w};
        float hh[4];
        #pragma unroll
        for (int r = 0; r < 4; r++) {
            float2 p0 = *(float2*)&acc[r][u2 * 2];       // (i, f)
            float2 p1 = *(float2*)&acc[r][u2 * 2 + 1];   // (g, o)
            float ig = fsig(p0.x);
            float fg = fsig(p0.y);
            float gg = ftanh(p1.x);
            float og = fsig(p1.y);
            float cn = fmaf(fg, cc[r], ig * gg);
            cc[r] = cn;
            hh[r] = og * ftanh(cn);
        }
        *(float4*)&g_c[hc * NR + nb]  = make_float4(cc[0], cc[1], cc[2], cc[3]);
        *(float4*)&hout[hc * NR + nb] = make_float4(hh[0], hh[1], hh[2], hh[3]);
    }
}

// ------------------------- transpose h_last to row-major -------------------------
__global__ void k_trh() {
    int idx = blockIdx.x * 256 + threadIdx.x;
    if (idx >= NR * HH) return;
    int n = idx / HH, k = idx % HH;
    g_hT[idx] = g_hA[k * NR + n];   // t=191 (odd parity) wrote into g_hA
}

// ------------------------- generic tiled GEMM: C = act(A @ W + b) -------------------------
__device__ __forceinline__ float* selbuf(int s) {
    switch (s) {
        case 0: return g_hT;
        case 1: return g_z1;
        case 2: return g_z2;
        default: return g_z3;
    }
}

__global__ __launch_bounds__(256) void k_gemm(int aSel, const float* __restrict__ W,
                                              const float* __restrict__ bias, int cSel,
                                              int M, int K, int Nn, int doRelu) {
    const float* A = selbuf(aSel);
    float* C = selbuf(cSel);
    __shared__ __align__(16) float As[16][68];
    __shared__ __align__(16) float Wsm[16][64];
    int tid = threadIdx.x;
    int n0 = blockIdx.x * 64, m0 = blockIdx.y * 64;
    int ty = tid / 16, tx = tid % 16;
    float acc[4][4];
    #pragma unroll
    for (int i = 0; i < 4; i++)
        #pragma unroll
        for (int j = 0; j < 4; j++) acc[i][j] = 0.f;

    for (int k0 = 0; k0 < K; k0 += 16) {
        {
            int mi = tid >> 2;
            int kq = tid & 3;
            int m = m0 + mi;
            #pragma unroll
            for (int j = 0; j < 4; j++) {
                int k = k0 + kq * 4 + j;
                As[kq * 4 + j][mi] = (m < M && k < K) ? A[m * K + k] : 0.f;
            }
        }
        {
            int kk = tid >> 6;
            int nn = tid & 63;
            int n = n0 + nn;
            #pragma unroll
            for (int j = 0; j < 4; j++) {
                int k = k0 + kk + j * 4;
                Wsm[kk + j * 4][nn] = (k < K && n < Nn) ? W[k * Nn + n] : 0.f;
            }
        }
        __syncthreads();
        #pragma unroll
        for (int kk = 0; kk < 16; kk++) {
            float4 a4 = *(const float4*)&As[kk][ty * 4];
            float4 b4 = *(const float4*)&Wsm[kk][tx * 4];
            acc[0][0] = fmaf(a4.x, b4.x, acc[0][0]);
            acc[0][1] = fmaf(a4.x, b4.y, acc[0][1]);
            acc[0][2] = fmaf(a4.x, b4.z, acc[0][2]);
            acc[0][3] = fmaf(a4.x, b4.w, acc[0][3]);
            acc[1][0] = fmaf(a4.y, b4.x, acc[1][0]);
            acc[1][1] = fmaf(a4.y, b4.y, acc[1][1]);
            acc[1][2] = fmaf(a4.y, b4.z, acc[1][2]);
            acc[1][3] = fmaf(a4.y, b4.w, acc[1][3]);
            acc[2][0] = fmaf(a4.z, b4.x, acc[2][0]);
            acc[2][1] = fmaf(a4.z, b4.y, acc[2][1]);
            acc[2][2] = fmaf(a4.z, b4.z, acc[2][2]);
            acc[2][3] = fmaf(a4.z, b4.w, acc[2][3]);
            acc[3][0] = fmaf(a4.w, b4.x, acc[3][0]);
            acc[3][1] = fmaf(a4.w, b4.y, acc[3][1]);
            acc[3][2] = fmaf(a4.w, b4.z, acc[3][2]);
            acc[3][3] = fmaf(a4.w, b4.w, acc[3][3]);
        }
        __syncthreads();
    }

    #pragma unroll
    for (int i = 0; i < 4; i++) {
        int m = m0 + ty * 4 + i;
        if (m >= M) continue;
        #pragma unroll
        for (int j = 0; j < 4; j++) {
            int n = n0 + tx * 4 + j;
            if (n >= Nn) continue;
            float v = acc[i][j] + bias[n];
            if (doRelu) v = fmaxf(v, 0.f);
            C[m * Nn + n] = v;
        }
    }
}

// ------------------------- final layer: sigmoid(z3 @ Wh4 + b) -> transposed out ----
__global__ void k_final(const float* __restrict__ Wh4, const float* __restrict__ bh4,
                        float* __restrict__ out) {
    __shared__ float zs[M1];
    int n = blockIdx.x;
    int tid = threadIdx.x;
    for (int k = tid; k < M1; k += 256) zs[k] = g_z3[n * M1 + k];
    __syncthreads();
    int w = tid >> 5, lane = tid & 31;
    #pragma unroll
    for (int oi = 0; oi < 3; oi++) {
        int o = w + oi * 8;
        float p = 0.f;
        for (int k = lane; k < M1; k += 32) p = fmaf(zs[k], Wh4[k * OD + o], p);
        #pragma unroll
        for (int off = 16; off; off >>= 1) p += __shfl_down_sync(0xffffffffu, p, off);
        if (lane == 0) {
            float y = fsig(p + bh4[o]);
            int b = n / LL, l = n % LL;
            out[(b * OD + o) * LL + l] = y;
        }
    }
}

// ------------------------- launcher -------------------------
extern "C" void kernel_launch(void* const* d_in, const int* in_sizes, int n_in,
                              void* d_out, int out_size) {
    const float* x    = (const float*)d_in[0];
    const float* Ahat = (const float*)d_in[1];
    const float* W1   = (const float*)d_in[2];
    const float* W2   = (const float*)d_in[3];
    const float* W_ih = (const float*)d_in[4];
    const float* W_hh = (const float*)d_in[5];
    const float* b_ih = (const float*)d_in[6];
    const float* b_hh = (const float*)d_in[7];
    const float* Wh1  = (const float*)d_in[8];
    const float* bh1  = (const float*)d_in[9];
    const float* Wh2  = (const float*)d_in[10];
    const float* bh2  = (const float*)d_in[11];
    const float* Wh3  = (const float*)d_in[12];
    const float* bh3  = (const float*)d_in[13];
    const float* Wh4  = (const float*)d_in[14];
    const float* bh4  = (const float*)d_in[15];
    float* out = (float*)d_out;

    cudaFuncSetAttribute(k_step2, cudaFuncAttributeMaxDynamicSharedMemorySize, SMEM_STEP);

    k_prep_pn<<<1, 512>>>(W1, W2);
    k_events<<<1, 512>>>();
    k_wihT<<<dim3(16, 63), dim3(32, 8)>>>(W_ih);
    k_wx2<<<dim3(16, 63), dim3(32, 8)>>>(W_hh);
    k_bias<<<(H4 + 255) / 256, 256>>>(b_ih, b_hh);
    k_tables<<<(H4 + 255) / 256, 256>>>();
    k_front<<<BB * TT, 128>>>(x, Ahat);
    k_seg<<<(TT * NR + 255) / 256, 256>>>();
    k_init<<<(2 * HH * NR + 255) / 256, 256>>>();

    dim3 sgrid(16, 15);  // hcol tiles x row tiles
    for (int t = 0; t < TT; t++) {
        k_step2<<<sgrid, 128, SMEM_STEP>>>(t, t & 1);
    }

    k_trh<<<(NR * HH + 255) / 256, 256>>>();

    k_gemm<<<dim3((M1 + 63) / 64, (NR + 63) / 64), 256>>>(0, Wh1, bh1, 1, NR, HH, M1, 1);
    k_gemm<<<dim3((M2 + 63) / 64, (NR + 63) / 64), 256>>>(1, Wh2, bh2, 2, NR, M1, M2, 1);
    k_gemm<<<dim3((M1 + 63) / 64, (NR + 63) / 64), 256>>>(2, Wh3, bh3, 3, NR, M2, M1, 1);
    k_final<<<NR, 256>>>(Wh4, bh4, out);
}

// round 4
// speedup vs baseline: 1.5224x; 1.5224x over previous
#include <cuda_runtime.h>
#include <math.h>

#define BB 4
#define TT 192
#define LL 120
#define GG 500
#define HH 500      // HL
#define H4 2000
#define NR 480      // B*L
#define OD 24
#define M1 3000
#define M2 1000

#define KS3 100
#define SMEM_STEP ((KS3*128 + KS3*32)*4)   // 64000 B

// ------------------------- scratch (device globals) -------------------------
__device__ float g_P[GG];
__device__ float g_Nv[GG];
__device__ float g_rho[GG];     // sorted breakpoints
__device__ float g_esign[GG];
__device__ int   g_ef[GG];
__device__ int   g_act0[GG];
__device__ int   g_nev[1];
__device__ float g_bias[H4];               // interleaved hc*4+gate
__device__ float g_Aseg[(GG + 1) * H4];    // interleaved
__device__ float g_Bseg[(GG + 1) * H4];    // interleaved
__device__ float g_WihT[GG * H4];   // [f][h]  (h in ORIGINAL gate*500+hc order)
__device__ float g_WX[HH * H4];     // [k][hc*4+gate]
__device__ float g_u[TT * NR];
__device__ float g_v[TT * NR];
__device__ int   g_seg[TT * NR];
__device__ float g_hA[HH * NR];     // h, k-major: [hcol][n]
__device__ float g_hB[HH * NR];
__device__ float g_c[HH * NR];      // c, k-major
__device__ float g_hT[NR * HH];     // h_last row-major for MLP
__device__ float g_z1[NR * M1];
__device__ float g_z2[NR * M2];
__device__ float g_z3[NR * M1];

// ------------------------- math helpers -------------------------
__device__ __forceinline__ float fsig(float x) {
    return __fdividef(1.f, 1.f + __expf(-x));
}
__device__ __forceinline__ float ftanh(float x) {
    float ax = fabsf(x);
    float t  = __expf(-2.f * ax);
    float r  = __fdividef(1.f - t, 1.f + t);
    return copysignf(r, x);
}

// ------------------------- setup #1: P,N + breakpoint events (1 block) ------
__global__ void k_setup1(const float* __restrict__ W1, const float* __restrict__ W2) {
    __shared__ float srho[GG];
    __shared__ float ssg[GG];
    __shared__ int   sf[GG];
    __shared__ int   cnt;
    int tid = threadIdx.x;
    // phase 1: P,N
    if (tid < GG) {
        float p = 0.f, n = 0.f;
        for (int g = 0; g < GG; g++) {
            float w = W1[g];
            float v = W2[g * GG + tid];
            p = fmaf(fmaxf(w, 0.f), v, p);
            n = fmaf(fmaxf(-w, 0.f), v, n);
        }
        g_P[tid]  = p;
        g_Nv[tid] = n;
    }
    if (tid == 0) cnt = 0;
    __syncthreads();
    // phase 2: classify + collect events
    if (tid < GG) {
        float p = g_P[tid], n = g_Nv[tid];
        int act0 = 0;
        float sgn = 0.f, rho = 0.f;
        if (n > 0.f) {
            if (p >= 0.f) { act0 = 1; }
            else { act0 = 0; rho = __fdividef(-p, n); sgn = 1.f; }
        } else if (n < 0.f) {
            if (p > 0.f) { act0 = 1; rho = __fdividef(p, -n); sgn = -1.f; }
            else { act0 = 0; }
        } else {
            act0 = (p > 0.f) ? 1 : 0;
        }
        g_act0[tid] = act0;
        if (sgn != 0.f) {
            int e = atomicAdd(&cnt, 1);
            srho[e] = rho; ssg[e] = sgn; sf[e] = tid;
        }
    }
    __syncthreads();
    int E = cnt;
    if (tid == 0) g_nev[0] = E;
    if (tid < E) {
        float r = srho[tid];
        int rank = 0;
        for (int j = 0; j < E; j++) {
            float rj = srho[j];
            rank += (rj < r) || (rj == r && j < tid);
        }
        g_rho[rank]   = r;
        g_esign[rank] = ssg[tid];
        g_ef[rank]    = sf[tid];
    }
}

// ------------------------- setup #2: both transposes + bias -----------------
// grid (16, 126), block (32, 8). y<63: WihT tiles; y>=63: WX tiles.
__global__ void k_trans(const float* __restrict__ W_ih, const float* __restrict__ W_hh,
                        const float* __restrict__ b_ih, const float* __restrict__ b_hh) {
    __shared__ float tle[32][33];
    int x = threadIdx.x, y = threadIdx.y;
    if (blockIdx.y < 63) {
        // g_WihT[f][h] = W_ih[h][f]
        int f0 = blockIdx.x * 32;
        int h0 = blockIdx.y * 32;
        for (int i = y; i < 32; i += 8) {
            int h = h0 + i, f = f0 + x;
            tle[i][x] = (h < H4 && f < GG) ? W_ih[h * GG + f] : 0.f;
        }
        __syncthreads();
        for (int i = y; i < 32; i += 8) {
            int f = f0 + i, h = h0 + x;
            if (f < GG && h < H4) g_WihT[f * H4 + h] = tle[x][i];
        }
    } else {
        // g_WX[k][hc*4+g] = W_hh[g*HH+hc][k]
        int k0 = blockIdx.x * 32;
        int r0 = (blockIdx.y - 63) * 32;
        for (int i = y; i < 32; i += 8) {
            int r = r0 + i, k = k0 + x;
            tle[i][x] = (r < H4 && k < HH) ? W_hh[r * HH + k] : 0.f;
        }
        __syncthreads();
        for (int i = y; i < 32; i += 8) {
            int k = k0 + i, r = r0 + x;
            if (k < HH && r < H4) {
                int g = r / HH, hc = r % HH;
                g_WX[k * H4 + hc * 4 + g] = tle[x][i];
            }
        }
        // bias (one block does it)
        if (blockIdx.x == 0 && blockIdx.y == 125) {
            int tid = y * 32 + x;
            for (int h = tid; h < H4; h += 256) {
                int q = (h % HH) * 4 + (h / HH);
                g_bias[q] = b_ih[h] + b_hh[h];
            }
        }
    }
}

// ------------------------- setup #3: tables + front(+seg) + h/c init --------
// grid: 8 (tables) + BB*TT (front) = 776 blocks, 256 threads
__global__ void k_prep3(const float* __restrict__ x, const float* __restrict__ Ahat) {
    __shared__ float xr[LL], sp[LL], sn[LL];
    int blk = blockIdx.x;
    int tid = threadIdx.x;
    if (blk < 8) {
        // segment prefix tables (interleaved cols)
        int h = blk * 256 + tid;   // ORIGINAL index gate*HH+hc
        if (h < H4) {
            int q = (h % HH) * 4 + (h / HH);
            float accA = 0.f, accB = 0.f;
            for (int f = 0; f < GG; f++) {
                if (g_act0[f]) {
                    float w = g_WihT[f * H4 + h];
                    accA = fmaf(w, g_P[f],  accA);
                    accB = fmaf(w, g_Nv[f], accB);
                }
            }
            g_Aseg[q] = accA;
            g_Bseg[q] = accB;
            int E = g_nev[0];
            for (int e = 0; e < E; e++) {
                int f = g_ef[e];
                float sgn = g_esign[e];
                float w = g_WihT[f * H4 + h] * sgn;
                accA = fmaf(w, g_P[f],  accA);
                accB = fmaf(w, g_Nv[f], accB);
                g_Aseg[(e + 1) * H4 + q] = accA;
                g_Bseg[(e + 1) * H4 + q] = accB;
            }
        }
    } else {
        // GCN front: u, v, seg for one (b,t)
        int bid = blk - 8;
        int b = bid / TT, t = bid % TT;
        if (tid < LL) xr[tid] = x[(b * TT + t) * LL + tid];
        __syncthreads();
        if (tid < LL) {
            float s = 0.f;
            const float* Ar = &Ahat[tid * LL];
            for (int l = 0; l < LL; l++) s = fmaf(Ar[l], xr[l], s);
            sp[tid] = fmaxf(s, 0.f);
            sn[tid] = fmaxf(-s, 0.f);
        }
        __syncthreads();
        if (tid < LL) {
            float uu = 0.f, vv = 0.f;
            const float* Ar = &Ahat[tid * LL];
            for (int l = 0; l < LL; l++) {
                uu = fmaf(Ar[l], sp[l], uu);
                vv = fmaf(Ar[l], sn[l], vv);
            }
            int n = b * LL + tid;
            int idx = t * NR + n;
            g_u[idx] = uu;
            g_v[idx] = vv;
            // segment lookup (depends only on this thread's uu,vv)
            int E = g_nev[0];
            int s;
            if (uu > 0.f) {
                float rho = vv / uu;
                int lo = 0, hi = E;
                while (lo < hi) {
                    int mid = (lo + hi) >> 1;
                    if (g_rho[mid] < rho) lo = mid + 1; else hi = mid;
                }
                s = lo;
            } else {
                s = (vv > 0.f) ? E : 0;
            }
            g_seg[idx] = s;
        }
    }
    // grid-stride zero init of h and c (all blocks participate)
    int stride = gridDim.x * 256;
    for (int idx = blk * 256 + tid; idx < 2 * HH * NR; idx += stride) {
        if (idx < HH * NR) g_hA[idx] = 0.f;
        else               g_c[idx - HH * NR] = 0.f;
    }
}

// ------------------------- fused LSTM step (scalar FFMA, 8x4 blocking) ------
// grid (16,15): 128 gate-cols (32 hc) x 32 rows. 128 threads:
// tx = tid&31 -> one hc (4 gate cols), ty = tid>>5 -> 8 rows.
__global__ __launch_bounds__(128) void k_step3(int t, int parity) {
    extern __shared__ float sm[];
    float* sW = sm;                 // [KS3][128]
    float* sH = sm + KS3 * 128;     // [KS3][32]
    const float* hin = parity ? g_hB : g_hA;
    float*      hout = parity ? g_hA : g_hB;
    int tid = threadIdx.x;
    int tx = tid & 31;
    int ty = tid >> 5;
    int hc0 = blockIdx.x * 32;
    int n0  = blockIdx.y * 32;
    int nb  = n0 + ty * 8;
    int gc0 = hc0 * 4 + tx * 4;
    int gb  = (gc0 + 3 < H4) ? gc0 : (H4 - 4);   // clamp for safe loads

    float acc[8][4];
    // prologue: gates_x = u*Aseg[s] + v*Bseg[s] + bias
    float4 bi4 = *(const float4*)&g_bias[gb];
    #pragma unroll
    for (int r = 0; r < 8; r++) {
        int pidx = t * NR + nb + r;
        float uu = g_u[pidx], vv = g_v[pidx];
        int s = g_seg[pidx];
        float4 a4 = *(const float4*)&g_Aseg[s * H4 + gb];
        float4 b4 = *(const float4*)&g_Bseg[s * H4 + gb];
        acc[r][0] = fmaf(uu, a4.x, fmaf(vv, b4.x, bi4.x));
        acc[r][1] = fmaf(uu, a4.y, fmaf(vv, b4.y, bi4.y));
        acc[r][2] = fmaf(uu, a4.z, fmaf(vv, b4.z, bi4.z));
        acc[r][3] = fmaf(uu, a4.w, fmaf(vv, b4.w, bi4.w));
    }

    #pragma unroll 1
    for (int k0 = 0; k0 < HH; k0 += KS3) {
        // load W slab: KS3 x 128 floats = KS3*32 float4
        #pragma unroll 1
        for (int e = tid; e < KS3 * 32; e += 128) {
            int kk = e >> 5, q = e & 31;
            int col = hc0 * 4 + q * 4;
            float4 v = make_float4(0.f, 0.f, 0.f, 0.f);
            if (col < H4) v = *(const float4*)&g_WX[(k0 + kk) * H4 + col];
            *(float4*)&sW[kk * 128 + q * 4] = v;
        }
        // load H slab: KS3 x 32 floats = KS3*8 float4
        #pragma unroll 1
        for (int e = tid; e < KS3 * 8; e += 128) {
            int kk = e >> 3, q = e & 7;
            *(float4*)&sH[kk * 32 + q * 4] =
                *(const float4*)&hin[(k0 + kk) * NR + n0 + q * 4];
        }
        __syncthreads();
        #pragma unroll 4
        for (int kk = 0; kk < KS3; kk++) {
            float4 w  = *(const float4*)&sW[kk * 128 + tx * 4];
            float4 h0 = *(const float4*)&sH[kk * 32 + ty * 8];
            float4 h1 = *(const float4*)&sH[kk * 32 + ty * 8 + 4];
            float hr[8] = {h0.x, h0.y, h0.z, h0.w, h1.x, h1.y, h1.z, h1.w};
            #pragma unroll
            for (int r = 0; r < 8; r++) {
                acc[r][0] = fmaf(hr[r], w.x, acc[r][0]);
                acc[r][1] = fmaf(hr[r], w.y, acc[r][1]);
                acc[r][2] = fmaf(hr[r], w.z, acc[r][2]);
                acc[r][3] = fmaf(hr[r], w.w, acc[r][3]);
            }
        }
        __syncthreads();
    }

    // epilogue: one hc x 8 rows per thread; gates (i,f,g,o) interleaved
    int hc = hc0 + tx;
    if (hc < HH) {
        int cb = hc * NR + nb;
        float4 c0 = *(float4*)&g_c[cb];
        float4 c1 = *(float4*)&g_c[cb + 4];
        float cc[8] = {c0.x, c0.y, c0.z, c0.w, c1.x, c1.y, c1.z, c1.w};
        float hh[8];
        #pragma unroll
        for (int r = 0; r < 8; r++) {
            float ig = fsig(acc[r][0]);
            float fg = fsig(acc[r][1]);
            float gg = ftanh(acc[r][2]);
            float og = fsig(acc[r][3]);
            float cn = fmaf(fg, cc[r], ig * gg);
            cc[r] = cn;
            hh[r] = og * ftanh(cn);
        }
        *(float4*)&g_c[cb]     = make_float4(cc[0], cc[1], cc[2], cc[3]);
        *(float4*)&g_c[cb + 4] = make_float4(cc[4], cc[5], cc[6], cc[7]);
        *(float4*)&hout[cb]     = make_float4(hh[0], hh[1], hh[2], hh[3]);
        *(float4*)&hout[cb + 4] = make_float4(hh[4], hh[5], hh[6], hh[7]);
    }
}

// ------------------------- transpose h_last to row-major -------------------------
__global__ void k_trh() {
    int idx = blockIdx.x * 256 + threadIdx.x;
    if (idx >= NR * HH) return;
    int n = idx / HH, k = idx % HH;
    g_hT[idx] = g_hA[k * NR + n];   // t=191 (odd parity) wrote into g_hA
}

// ------------------------- generic tiled GEMM: C = act(A @ W + b) -------------------------
__device__ __forceinline__ float* selbuf(int s) {
    switch (s) {
        case 0: return g_hT;
        case 1: return g_z1;
        case 2: return g_z2;
        default: return g_z3;
    }
}

__global__ __launch_bounds__(256) void k_gemm(int aSel, const float* __restrict__ W,
                                              const float* __restrict__ bias, int cSel,
                                              int M, int K, int Nn, int doRelu) {
    const float* A = selbuf(aSel);
    float* C = selbuf(cSel);
    __shared__ __align__(16) float As[16][68];
    __shared__ __align__(16) float Wsm[16][64];
    int tid = threadIdx.x;
    int n0 = blockIdx.x * 64, m0 = blockIdx.y * 64;
    int ty = tid / 16, tx = tid % 16;
    float acc[4][4];
    #pragma unroll
    for (int i = 0; i < 4; i++)
        #pragma unroll
        for (int j = 0; j < 4; j++) acc[i][j] = 0.f;

    for (int k0 = 0; k0 < K; k0 += 16) {
        {
            int mi = tid >> 2;
            int kq = tid & 3;
            int m = m0 + mi;
            #pragma unroll
            for (int j = 0; j < 4; j++) {
                int k = k0 + kq * 4 + j;
                As[kq * 4 + j][mi] = (m < M && k < K) ? A[m * K + k] : 0.f;
            }
        }
        {
            int kk = tid >> 6;
            int nn = tid & 63;
            int n = n0 + nn;
            #pragma unroll
            for (int j = 0; j < 4; j++) {
                int k = k0 + kk + j * 4;
                Wsm[kk + j * 4][nn] = (k < K && n < Nn) ? W[k * Nn + n] : 0.f;
            }
        }
        __syncthreads();
        #pragma unroll
        for (int kk = 0; kk < 16; kk++) {
            float4 a4 = *(const float4*)&As[kk][ty * 4];
            float4 b4 = *(const float4*)&Wsm[kk][tx * 4];
            acc[0][0] = fmaf(a4.x, b4.x, acc[0][0]);
            acc[0][1] = fmaf(a4.x, b4.y, acc[0][1]);
            acc[0][2] = fmaf(a4.x, b4.z, acc[0][2]);
            acc[0][3] = fmaf(a4.x, b4.w, acc[0][3]);
            acc[1][0] = fmaf(a4.y, b4.x, acc[1][0]);
            acc[1][1] = fmaf(a4.y, b4.y, acc[1][1]);
            acc[1][2] = fmaf(a4.y, b4.z, acc[1][2]);
            acc[1][3] = fmaf(a4.y, b4.w, acc[1][3]);
            acc[2][0] = fmaf(a4.z, b4.x, acc[2][0]);
            acc[2][1] = fmaf(a4.z, b4.y, acc[2][1]);
            acc[2][2] = fmaf(a4.z, b4.z, acc[2][2]);
            acc[2][3] = fmaf(a4.z, b4.w, acc[2][3]);
            acc[3][0] = fmaf(a4.w, b4.x, acc[3][0]);
            acc[3][1] = fmaf(a4.w, b4.y, acc[3][1]);
            acc[3][2] = fmaf(a4.w, b4.z, acc[3][2]);
            acc[3][3] = fmaf(a4.w, b4.w, acc[3][3]);
        }
        __syncthreads();
    }

    #pragma unroll
    for (int i = 0; i < 4; i++) {
        int m = m0 + ty * 4 + i;
        if (m >= M) continue;
        #pragma unroll
        for (int j = 0; j < 4; j++) {
            int n = n0 + tx * 4 + j;
            if (n >= Nn) continue;
            float v = acc[i][j] + bias[n];
            if (doRelu) v = fmaxf(v, 0.f);
            C[m * Nn + n] = v;
        }
    }
}

// ------------------------- final layer: sigmoid(z3 @ Wh4 + b) -> transposed out ----
__global__ void k_final(const float* __restrict__ Wh4, const float* __restrict__ bh4,
                        float* __restrict__ out) {
    __shared__ float zs[M1];
    int n = blockIdx.x;
    int tid = threadIdx.x;
    for (int k = tid; k < M1; k += 256) zs[k] = g_z3[n * M1 + k];
    __syncthreads();
    int w = tid >> 5, lane = tid & 31;
    #pragma unroll
    for (int oi = 0; oi < 3; oi++) {
        int o = w + oi * 8;
        float p = 0.f;
        for (int k = lane; k < M1; k += 32) p = fmaf(zs[k], Wh4[k * OD + o], p);
        #pragma unroll
        for (int off = 16; off; off >>= 1) p += __shfl_down_sync(0xffffffffu, p, off);
        if (lane == 0) {
            float y = fsig(p + bh4[o]);
            int b = n / LL, l = n % LL;
            out[(b * OD + o) * LL + l] = y;
        }
    }
}

// ------------------------- launcher -------------------------
extern "C" void kernel_launch(void* const* d_in, const int* in_sizes, int n_in,
                              void* d_out, int out_size) {
    const float* x    = (const float*)d_in[0];
    const float* Ahat = (const float*)d_in[1];
    const float* W1   = (const float*)d_in[2];
    const float* W2   = (const float*)d_in[3];
    const float* W_ih = (const float*)d_in[4];
    const float* W_hh = (const float*)d_in[5];
    const float* b_ih = (const float*)d_in[6];
    const float* b_hh = (const float*)d_in[7];
    const float* Wh1  = (const float*)d_in[8];
    const float* bh1  = (const float*)d_in[9];
    const float* Wh2  = (const float*)d_in[10];
    const float* bh2  = (const float*)d_in[11];
    const float* Wh3  = (const float*)d_in[12];
    const float* bh3  = (const float*)d_in[13];
    const float* Wh4  = (const float*)d_in[14];
    const float* bh4  = (const float*)d_in[15];
    float* out = (float*)d_out;

    cudaFuncSetAttribute(k_step3, cudaFuncAttributeMaxDynamicSharedMemorySize, SMEM_STEP);

    // exactly 3 setup launches so k_step3(t=0) is launch #4 (ncu target)
    k_setup1<<<1, 512>>>(W1, W2);
    k_trans<<<dim3(16, 126), dim3(32, 8)>>>(W_ih, W_hh, b_ih, b_hh);
    k_prep3<<<8 + BB * TT, 256>>>(x, Ahat);

    dim3 sgrid(16, 15);
    for (int t = 0; t < TT; t++) {
        k_step3<<<sgrid, 128, SMEM_STEP>>>(t, t & 1);
    }

    k_trh<<<(NR * HH + 255) / 256, 256>>>();

    k_gemm<<<dim3((M1 + 63) / 64, (NR + 63) / 64), 256>>>(0, Wh1, bh1, 1, NR, HH, M1, 1);
    k_gemm<<<dim3((M2 + 63) / 64, (NR + 63) / 64), 256>>>(1, Wh2, bh2, 2, NR, M1, M2, 1);
    k_gemm<<<dim3((M1 + 63) / 64, (NR + 63) / 64), 256>>>(2, Wh3, bh3, 3, NR, M2, M1, 1);
    k_final<<<NR, 256>>>(Wh4, bh4, out);
}

// round 5
// speedup vs baseline: 2.6241x; 1.7236x over previous
#include <cuda_runtime.h>
#include <math.h>

#define BB 4
#define TT 192
#define LL 120
#define GG 500
#define HH 500      // HL
#define H4 2000
#define NR 480      // B*L
#define OD 24
#define M1 3000
#define M2 1000

#define KS4 50
#define NSLAB (HH / KS4)                       // 10
#define SLABF (KS4*128 + KS4*32)               // floats per buffer (8000)
#define SMEM_STEP (2 * SLABF * 4)              // 64000 B

// ------------------------- scratch (device globals) -------------------------
__device__ float g_P[GG];
__device__ float g_Nv[GG];
__device__ float g_rho[GG];
__device__ float g_esign[GG];
__device__ int   g_ef[GG];
__device__ int   g_act0[GG];
__device__ int   g_nev[1];
__device__ __align__(16) float g_bias[H4];             // interleaved hc*4+gate
__device__ __align__(16) float g_Aseg[(GG + 1) * H4];  // interleaved
__device__ __align__(16) float g_Bseg[(GG + 1) * H4];  // interleaved
__device__ __align__(16) float g_WihT[GG * H4];        // [f][h] (orig gate*500+hc order)
__device__ __align__(16) float g_WX[HH * H4];          // [k][hc*4+gate]
__device__ __align__(16) float g_u[TT * NR];
__device__ __align__(16) float g_v[TT * NR];
__device__ __align__(16) int   g_seg[TT * NR];
__device__ __align__(16) float g_hA[HH * NR];          // h, k-major: [hcol][n]
__device__ __align__(16) float g_hB[HH * NR];
__device__ __align__(16) float g_c[HH * NR];           // c, k-major
__device__ __align__(16) float g_hT[NR * HH];
__device__ __align__(16) float g_z1[NR * M1];
__device__ __align__(16) float g_z2[NR * M2];
__device__ __align__(16) float g_z3[NR * M1];

// ------------------------- math helpers -------------------------
__device__ __forceinline__ float fsig(float x) {
    return __fdividef(1.f, 1.f + __expf(-x));
}
__device__ __forceinline__ float ftanh(float x) {
    float ax = fabsf(x);
    float t  = __expf(-2.f * ax);
    float r  = __fdividef(1.f - t, 1.f + t);
    return copysignf(r, x);
}

__device__ __forceinline__ void cp16(unsigned dst_smem, const float* src) {
    asm volatile("cp.async.cg.shared.global [%0], [%1], 16;" :: "r"(dst_smem), "l"(src));
}
__device__ __forceinline__ void cp_commit() {
    asm volatile("cp.async.commit_group;");
}
template <int N>
__device__ __forceinline__ void cp_wait() {
    asm volatile("cp.async.wait_group %0;" :: "n"(N));
}

// ------------------------- setup #1: P,N + breakpoint events (1 block) ------
__global__ void k_setup1(const float* __restrict__ W1, const float* __restrict__ W2) {
    __shared__ float srho[GG];
    __shared__ float ssg[GG];
    __shared__ int   sf[GG];
    __shared__ int   cnt;
    int tid = threadIdx.x;
    if (tid < GG) {
        float p = 0.f, n = 0.f;
        for (int g = 0; g < GG; g++) {
            float w = W1[g];
            float v = W2[g * GG + tid];
            p = fmaf(fmaxf(w, 0.f), v, p);
            n = fmaf(fmaxf(-w, 0.f), v, n);
        }
        g_P[tid]  = p;
        g_Nv[tid] = n;
    }
    if (tid == 0) cnt = 0;
    __syncthreads();
    if (tid < GG) {
        float p = g_P[tid], n = g_Nv[tid];
        int act0 = 0;
        float sgn = 0.f, rho = 0.f;
        if (n > 0.f) {
            if (p >= 0.f) { act0 = 1; }
            else { act0 = 0; rho = __fdividef(-p, n); sgn = 1.f; }
        } else if (n < 0.f) {
            if (p > 0.f) { act0 = 1; rho = __fdividef(p, -n); sgn = -1.f; }
            else { act0 = 0; }
        } else {
            act0 = (p > 0.f) ? 1 : 0;
        }
        g_act0[tid] = act0;
        if (sgn != 0.f) {
            int e = atomicAdd(&cnt, 1);
            srho[e] = rho; ssg[e] = sgn; sf[e] = tid;
        }
    }
    __syncthreads();
    int E = cnt;
    if (tid == 0) g_nev[0] = E;
    if (tid < E) {
        float r = srho[tid];
        int rank = 0;
        for (int j = 0; j < E; j++) {
            float rj = srho[j];
            rank += (rj < r) || (rj == r && j < tid);
        }
        g_rho[rank]   = r;
        g_esign[rank] = ssg[tid];
        g_ef[rank]    = sf[tid];
    }
}

// ------------------------- setup #2: both transposes + bias -----------------
__global__ void k_trans(const float* __restrict__ W_ih, const float* __restrict__ W_hh,
                        const float* __restrict__ b_ih, const float* __restrict__ b_hh) {
    __shared__ float tle[32][33];
    int x = threadIdx.x, y = threadIdx.y;
    if (blockIdx.y < 63) {
        int f0 = blockIdx.x * 32;
        int h0 = blockIdx.y * 32;
        for (int i = y; i < 32; i += 8) {
            int h = h0 + i, f = f0 + x;
            tle[i][x] = (h < H4 && f < GG) ? W_ih[h * GG + f] : 0.f;
        }
        __syncthreads();
        for (int i = y; i < 32; i += 8) {
            int f = f0 + i, h = h0 + x;
            if (f < GG && h < H4) g_WihT[f * H4 + h] = tle[x][i];
        }
    } else {
        int k0 = blockIdx.x * 32;
        int r0 = (blockIdx.y - 63) * 32;
        for (int i = y; i < 32; i += 8) {
            int r = r0 + i, k = k0 + x;
            tle[i][x] = (r < H4 && k < HH) ? W_hh[r * HH + k] : 0.f;
        }
        __syncthreads();
        for (int i = y; i < 32; i += 8) {
            int k = k0 + i, r = r0 + x;
            if (k < HH && r < H4) {
                int g = r / HH, hc = r % HH;
                g_WX[k * H4 + hc * 4 + g] = tle[x][i];
            }
        }
        if (blockIdx.x == 0 && blockIdx.y == 125) {
            int tid = y * 32 + x;
            for (int h = tid; h < H4; h += 256) {
                int q = (h % HH) * 4 + (h / HH);
                g_bias[q] = b_ih[h] + b_hh[h];
            }
        }
    }
}

// ------------------------- setup #3: tables + front(+seg) + h/c init --------
__global__ void k_prep3(const float* __restrict__ x, const float* __restrict__ Ahat) {
    __shared__ float xr[LL], sp[LL], sn[LL];
    int blk = blockIdx.x;
    int tid = threadIdx.x;
    if (blk < 8) {
        int h = blk * 256 + tid;
        if (h < H4) {
            int q = (h % HH) * 4 + (h / HH);
            float accA = 0.f, accB = 0.f;
            for (int f = 0; f < GG; f++) {
                if (g_act0[f]) {
                    float w = g_WihT[f * H4 + h];
                    accA = fmaf(w, g_P[f],  accA);
                    accB = fmaf(w, g_Nv[f], accB);
                }
            }
            g_Aseg[q] = accA;
            g_Bseg[q] = accB;
            int E = g_nev[0];
            for (int e = 0; e < E; e++) {
                int f = g_ef[e];
                float sgn = g_esign[e];
                float w = g_WihT[f * H4 + h] * sgn;
                accA = fmaf(w, g_P[f],  accA);
                accB = fmaf(w, g_Nv[f], accB);
                g_Aseg[(e + 1) * H4 + q] = accA;
                g_Bseg[(e + 1) * H4 + q] = accB;
            }
        }
    } else {
        int bid = blk - 8;
        int b = bid / TT, t = bid % TT;
        if (tid < LL) xr[tid] = x[(b * TT + t) * LL + tid];
        __syncthreads();
        if (tid < LL) {
            float s = 0.f;
            const float* Ar = &Ahat[tid * LL];
            for (int l = 0; l < LL; l++) s = fmaf(Ar[l], xr[l], s);
            sp[tid] = fmaxf(s, 0.f);
            sn[tid] = fmaxf(-s, 0.f);
        }
        __syncthreads();
        if (tid < LL) {
            float uu = 0.f, vv = 0.f;
            const float* Ar = &Ahat[tid * LL];
            for (int l = 0; l < LL; l++) {
                uu = fmaf(Ar[l], sp[l], uu);
                vv = fmaf(Ar[l], sn[l], vv);
            }
            int n = b * LL + tid;
            int idx = t * NR + n;
            g_u[idx] = uu;
            g_v[idx] = vv;
            int E = g_nev[0];
            int s;
            if (uu > 0.f) {
                float rho = vv / uu;
                int lo = 0, hi = E;
                while (lo < hi) {
                    int mid = (lo + hi) >> 1;
                    if (g_rho[mid] < rho) lo = mid + 1; else hi = mid;
                }
                s = lo;
            } else {
                s = (vv > 0.f) ? E : 0;
            }
            g_seg[idx] = s;
        }
    }
    int stride = gridDim.x * 256;
    for (int idx = blk * 256 + tid; idx < 2 * HH * NR; idx += stride) {
        if (idx < HH * NR) g_hA[idx] = 0.f;
        else               g_c[idx - HH * NR] = 0.f;
    }
}

// ------------------------- fused LSTM step (cp.async double-buffered) -------
// grid (16,15): 128 gate-cols (32 hc) x 32 rows. 128 threads:
// tx = tid&31 -> one hc (4 gate cols), ty = tid>>5 -> 8 rows.
__global__ __launch_bounds__(128) void k_step4(int t, int parity) {
    extern __shared__ __align__(16) float sm[];
    const float* hin = parity ? g_hB : g_hA;
    float*      hout = parity ? g_hA : g_hB;
    int tid = threadIdx.x;
    int tx = tid & 31;
    int ty = tid >> 5;
    int hc0 = blockIdx.x * 32;
    int n0  = blockIdx.y * 32;
    int nb  = n0 + ty * 8;
    int gc0 = hc0 * 4 + tx * 4;
    int gb  = (gc0 + 3 < H4) ? gc0 : (H4 - 4);

    // smem buffers: buf b at sm + b*SLABF; W = [KS4][128] then H = [KS4][32]
    unsigned smbase = (unsigned)__cvta_generic_to_shared(sm);

    // slab loader via cp.async (W: KS4*32 float4, H: KS4*8 float4)
    auto load_slab = [&](int ks, int buf) {
        int k0 = ks * KS4;
        float* bufp = sm + buf * SLABF;
        unsigned bW = smbase + (unsigned)(buf * SLABF) * 4u;
        unsigned bH = bW + KS4 * 128 * 4u;
        #pragma unroll 1
        for (int e = tid; e < KS4 * 32; e += 128) {
            int kk = e >> 5, q = e & 31;
            int col = hc0 * 4 + q * 4;
            if (col + 3 < H4) {
                cp16(bW + (unsigned)(kk * 128 + q * 4) * 4u, &g_WX[(k0 + kk) * H4 + col]);
            } else {
                *(float4*)&bufp[kk * 128 + q * 4] = make_float4(0.f, 0.f, 0.f, 0.f);
            }
        }
        #pragma unroll 1
        for (int e = tid; e < KS4 * 8; e += 128) {
            int kk = e >> 3, q = e & 7;
            cp16(bH + (unsigned)(kk * 32 + q * 4) * 4u, &hin[(k0 + kk) * NR + n0 + q * 4]);
        }
        cp_commit();
    };

    load_slab(0, 0);

    float acc[8][4];
    // prologue: gates_x = u*Aseg[s] + v*Bseg[s] + bias (overlaps with slab-0 load)
    float4 bi4 = *(const float4*)&g_bias[gb];
    #pragma unroll
    for (int r = 0; r < 8; r++) {
        int pidx = t * NR + nb + r;
        float uu = g_u[pidx], vv = g_v[pidx];
        int s = g_seg[pidx];
        float4 a4 = *(const float4*)&g_Aseg[s * H4 + gb];
        float4 b4 = *(const float4*)&g_Bseg[s * H4 + gb];
        acc[r][0] = fmaf(uu, a4.x, fmaf(vv, b4.x, bi4.x));
        acc[r][1] = fmaf(uu, a4.y, fmaf(vv, b4.y, bi4.y));
        acc[r][2] = fmaf(uu, a4.z, fmaf(vv, b4.z, bi4.z));
        acc[r][3] = fmaf(uu, a4.w, fmaf(vv, b4.w, bi4.w));
    }

    #pragma unroll 1
    for (int s = 0; s < NSLAB; s++) {
        int buf = s & 1;
        if (s + 1 < NSLAB) {
            load_slab(s + 1, buf ^ 1);
            cp_wait<1>();   // slab s complete, slab s+1 may be in flight
        } else {
            cp_wait<0>();
        }
        __syncthreads();
        const float* sW = sm + buf * SLABF;
        const float* sH = sW + KS4 * 128;
        #pragma unroll 5
        for (int kk = 0; kk < KS4; kk++) {
            float4 w  = *(const float4*)&sW[kk * 128 + tx * 4];
            float4 h0 = *(const float4*)&sH[kk * 32 + ty * 8];
            float4 h1 = *(const float4*)&sH[kk * 32 + ty * 8 + 4];
            float hr[8] = {h0.x, h0.y, h0.z, h0.w, h1.x, h1.y, h1.z, h1.w};
            #pragma unroll
            for (int r = 0; r < 8; r++) {
                acc[r][0] = fmaf(hr[r], w.x, acc[r][0]);
                acc[r][1] = fmaf(hr[r], w.y, acc[r][1]);
                acc[r][2] = fmaf(hr[r], w.z, acc[r][2]);
                acc[r][3] = fmaf(hr[r], w.w, acc[r][3]);
            }
        }
        __syncthreads();   // compute done before buffer reuse
    }

    // epilogue
    int hc = hc0 + tx;
    if (hc < HH) {
        int cb = hc * NR + nb;
        float4 c0 = *(float4*)&g_c[cb];
        float4 c1 = *(float4*)&g_c[cb + 4];
        float cc[8] = {c0.x, c0.y, c0.z, c0.w, c1.x, c1.y, c1.z, c1.w};
        float hh[8];
        #pragma unroll
        for (int r = 0; r < 8; r++) {
            float ig = fsig(acc[r][0]);
            float fg = fsig(acc[r][1]);
            float gg = ftanh(acc[r][2]);
            float og = fsig(acc[r][3]);
            float cn = fmaf(fg, cc[r], ig * gg);
            cc[r] = cn;
            hh[r] = og * ftanh(cn);
        }
        *(float4*)&g_c[cb]     = make_float4(cc[0], cc[1], cc[2], cc[3]);
        *(float4*)&g_c[cb + 4] = make_float4(cc[4], cc[5], cc[6], cc[7]);
        *(float4*)&hout[cb]     = make_float4(hh[0], hh[1], hh[2], hh[3]);
        *(float4*)&hout[cb + 4] = make_float4(hh[4], hh[5], hh[6], hh[7]);
    }
}

// ------------------------- transpose h_last to row-major -------------------------
__global__ void k_trh() {
    int idx = blockIdx.x * 256 + threadIdx.x;
    if (idx >= NR * HH) return;
    int n = idx / HH, k = idx % HH;
    g_hT[idx] = g_hA[k * NR + n];   // t=191 (odd parity) wrote into g_hA
}

// ------------------------- generic tiled GEMM: C = act(A @ W + b) -------------------------
__device__ __forceinline__ float* selbuf(int s) {
    switch (s) {
        case 0: return g_hT;
        case 1: return g_z1;
        case 2: return g_z2;
        default: return g_z3;
    }
}

__global__ __launch_bounds__(256) void k_gemm(int aSel, const float* __restrict__ W,
                                              const float* __restrict__ bias, int cSel,
                                              int M, int K, int Nn, int doRelu) {
    const float* A = selbuf(aSel);
    float* C = selbuf(cSel);
    __shared__ __align__(16) float As[16][68];
    __shared__ __align__(16) float Wsm[16][64];
    int tid = threadIdx.x;
    int n0 = blockIdx.x * 64, m0 = blockIdx.y * 64;
    int ty = tid / 16, tx = tid % 16;
    float acc[4][4];
    #pragma unroll
    for (int i = 0; i < 4; i++)
        #pragma unroll
        for (int j = 0; j < 4; j++) acc[i][j] = 0.f;

    for (int k0 = 0; k0 < K; k0 += 16) {
        {
            int mi = tid >> 2;
            int kq = tid & 3;
            int m = m0 + mi;
            #pragma unroll
            for (int j = 0; j < 4; j++) {
                int k = k0 + kq * 4 + j;
                As[kq * 4 + j][mi] = (m < M && k < K) ? A[m * K + k] : 0.f;
            }
        }
        {
            int kk = tid >> 6;
            int nn = tid & 63;
            int n = n0 + nn;
            #pragma unroll
            for (int j = 0; j < 4; j++) {
                int k = k0 + kk + j * 4;
                Wsm[kk + j * 4][nn] = (k < K && n < Nn) ? W[k * Nn + n] : 0.f;
            }
        }
        __syncthreads();
        #pragma unroll
        for (int kk = 0; kk < 16; kk++) {
            float4 a4 = *(const float4*)&As[kk][ty * 4];
            float4 b4 = *(const float4*)&Wsm[kk][tx * 4];
            acc[0][0] = fmaf(a4.x, b4.x, acc[0][0]);
            acc[0][1] = fmaf(a4.x, b4.y, acc[0][1]);
            acc[0][2] = fmaf(a4.x, b4.z, acc[0][2]);
            acc[0][3] = fmaf(a4.x, b4.w, acc[0][3]);
            acc[1][0] = fmaf(a4.y, b4.x, acc[1][0]);
            acc[1][1] = fmaf(a4.y, b4.y, acc[1][1]);
            acc[1][2] = fmaf(a4.y, b4.z, acc[1][2]);
            acc[1][3] = fmaf(a4.y, b4.w, acc[1][3]);
            acc[2][0] = fmaf(a4.z, b4.x, acc[2][0]);
            acc[2][1] = fmaf(a4.z, b4.y, acc[2][1]);
            acc[2][2] = fmaf(a4.z, b4.z, acc[2][2]);
            acc[2][3] = fmaf(a4.z, b4.w, acc[2][3]);
            acc[3][0] = fmaf(a4.w, b4.x, acc[3][0]);
            acc[3][1] = fmaf(a4.w, b4.y, acc[3][1]);
            acc[3][2] = fmaf(a4.w, b4.z, acc[3][2]);
            acc[3][3] = fmaf(a4.w, b4.w, acc[3][3]);
        }
        __syncthreads();
    }

    #pragma unroll
    for (int i = 0; i < 4; i++) {
        int m = m0 + ty * 4 + i;
        if (m >= M) continue;
        #pragma unroll
        for (int j = 0; j < 4; j++) {
            int n = n0 + tx * 4 + j;
            if (n >= Nn) continue;
            float v = acc[i][j] + bias[n];
            if (doRelu) v = fmaxf(v, 0.f);
            C[m * Nn + n] = v;
        }
    }
}

// ------------------------- final layer -------------------------
__global__ void k_final(const float* __restrict__ Wh4, const float* __restrict__ bh4,
                        float* __restrict__ out) {
    __shared__ float zs[M1];
    int n = blockIdx.x;
    int tid = threadIdx.x;
    for (int k = tid; k < M1; k += 256) zs[k] = g_z3[n * M1 + k];
    __syncthreads();
    int w = tid >> 5, lane = tid & 31;
    #pragma unroll
    for (int oi = 0; oi < 3; oi++) {
        int o = w + oi * 8;
        float p = 0.f;
        for (int k = lane; k < M1; k += 32) p = fmaf(zs[k], Wh4[k * OD + o], p);
        #pragma unroll
        for (int off = 16; off; off >>= 1) p += __shfl_down_sync(0xffffffffu, p, off);
        if (lane == 0) {
            float y = fsig(p + bh4[o]);
            int b = n / LL, l = n % LL;
            out[(b * OD + o) * LL + l] = y;
        }
    }
}

// ------------------------- launcher -------------------------
extern "C" void kernel_launch(void* const* d_in, const int* in_sizes, int n_in,
                              void* d_out, int out_size) {
    const float* x    = (const float*)d_in[0];
    const float* Ahat = (const float*)d_in[1];
    const float* W1   = (const float*)d_in[2];
    const float* W2   = (const float*)d_in[3];
    const float* W_ih = (const float*)d_in[4];
    const float* W_hh = (const float*)d_in[5];
    const float* b_ih = (const float*)d_in[6];
    const float* b_hh = (const float*)d_in[7];
    const float* Wh1  = (const float*)d_in[8];
    const float* bh1  = (const float*)d_in[9];
    const float* Wh2  = (const float*)d_in[10];
    const float* bh2  = (const float*)d_in[11];
    const float* Wh3  = (const float*)d_in[12];
    const float* bh3  = (const float*)d_in[13];
    const float* Wh4  = (const float*)d_in[14];
    const float* bh4  = (const float*)d_in[15];
    float* out = (float*)d_out;

    cudaFuncSetAttribute(k_step4, cudaFuncAttributeMaxDynamicSharedMemorySize, SMEM_STEP);

    // exactly 3 setup launches so k_step4(t=0) is launch #4 (ncu target)
    k_setup1<<<1, 512>>>(W1, W2);
    k_trans<<<dim3(16, 126), dim3(32, 8)>>>(W_ih, W_hh, b_ih, b_hh);
    k_prep3<<<8 + BB * TT, 256>>>(x, Ahat);

    dim3 sgrid(16, 15);
    for (int t = 0; t < TT; t++) {
        k_step4<<<sgrid, 128, SMEM_STEP>>>(t, t & 1);
    }

    k_trh<<<(NR * HH + 255) / 256, 256>>>();

    k_gemm<<<dim3((M1 + 63) / 64, (NR + 63) / 64), 256>>>(0, Wh1, bh1, 1, NR, HH, M1, 1);
    k_gemm<<<dim3((M2 + 63) / 64, (NR + 63) / 64), 256>>>(1, Wh2, bh2, 2, NR, M1, M2, 1);
    k_gemm<<<dim3((M1 + 63) / 64, (NR + 63) / 64), 256>>>(2, Wh3, bh3, 3, NR, M2, M1, 1);
    k_final<<<NR, 256>>>(Wh4, bh4, out);
}

// round 6
// speedup vs baseline: 3.9241x; 1.4954x over previous
#include <cuda_runtime.h>
#include <math.h>

#define BB 4
#define TT 192
#define LL 120
#define GG 500
#define HH 500      // HL
#define H4 2000
#define H4P 2048    // padded gate-col count
#define KP 512      // padded K
#define NR 480      // B*L
#define OD 24
#define M1 3000
#define M2 1000

// step kernel tiling
#define KS5 64
#define NSLAB5 (KP / KS5)            // 8
#define WPAD 136
#define HPAD 56
#define SLABF5 (KS5*WPAD + KS5*HPAD) // 12288 floats
#define SMEM_STEP (2 * SLABF5 * 4)   // 98304 B

// ------------------------- scratch (device globals) -------------------------
__device__ float g_P[GG];
__device__ float g_Nv[GG];
__device__ float g_rho[GG];
__device__ float g_esign[GG];
__device__ int   g_ef[GG];
__device__ int   g_act0[GG];
__device__ int   g_nev[1];
__device__ __align__(16) float g_bias[H4P];              // interleaved hc*4+gate
__device__ __align__(16) float g_Aseg[(GG + 1) * H4P];   // interleaved
__device__ __align__(16) float g_Bseg[(GG + 1) * H4P];   // interleaved
__device__ __align__(16) float g_WihT[GG * H4];          // [f][h] (orig order)
__device__ __align__(16) float g_WX[KP * H4P];           // [k][hc*4+gate], tf32-rounded
__device__ __align__(16) float g_u[TT * NR];
__device__ __align__(16) float g_v[TT * NR];
__device__ __align__(16) int   g_seg[TT * NR];
__device__ __align__(16) float g_hA[KP * NR];            // h, k-major (pad rows zero)
__device__ __align__(16) float g_hB[KP * NR];
__device__ __align__(16) float g_c[HH * NR];             // c, k-major
__device__ __align__(16) float g_hT[NR * HH];
__device__ __align__(16) float g_z1[NR * M1];
__device__ __align__(16) float g_z2[NR * M2];
__device__ __align__(16) float g_z3[NR * M1];

// ------------------------- math helpers -------------------------
__device__ __forceinline__ float fsig(float x) {
    return __fdividef(1.f, 1.f + __expf(-x));
}
__device__ __forceinline__ float ftanh(float x) {
    float ax = fabsf(x);
    float t  = __expf(-2.f * ax);
    float r  = __fdividef(1.f - t, 1.f + t);
    return copysignf(r, x);
}
__device__ __forceinline__ float tf32r(float x) {
    unsigned r;
    asm("cvt.rna.tf32.f32 %0, %1;" : "=r"(r) : "f"(x));
    return __uint_as_float(r);
}

__device__ __forceinline__ void cp16(unsigned dst_smem, const float* src) {
    asm volatile("cp.async.cg.shared.global [%0], [%1], 16;" :: "r"(dst_smem), "l"(src));
}
__device__ __forceinline__ void cp_commit() {
    asm volatile("cp.async.commit_group;");
}
template <int N>
__device__ __forceinline__ void cp_wait() {
    asm volatile("cp.async.wait_group %0;" :: "n"(N));
}

// tf32 m16n8k8 MMA (fp32 accumulate)
__device__ __forceinline__ void mma8(float* d, const unsigned* a, const unsigned* b) {
    asm volatile(
        "mma.sync.aligned.m16n8k8.row.col.f32.tf32.tf32.f32 "
        "{%0,%1,%2,%3}, {%4,%5,%6,%7}, {%8,%9}, {%0,%1,%2,%3};"
        : "+f"(d[0]), "+f"(d[1]), "+f"(d[2]), "+f"(d[3])
        : "r"(a[0]), "r"(a[1]), "r"(a[2]), "r"(a[3]), "r"(b[0]), "r"(b[1]));
}

// ------------------------- setup #1: P,N + breakpoint events (1 block) ------
__global__ void k_setup1(const float* __restrict__ W1, const float* __restrict__ W2) {
    __shared__ float srho[GG];
    __shared__ float ssg[GG];
    __shared__ int   sf[GG];
    __shared__ int   cnt;
    int tid = threadIdx.x;
    if (tid < GG) {
        float p = 0.f, n = 0.f;
        for (int g = 0; g < GG; g++) {
            float w = W1[g];
            float v = W2[g * GG + tid];
            p = fmaf(fmaxf(w, 0.f), v, p);
            n = fmaf(fmaxf(-w, 0.f), v, n);
        }
        g_P[tid]  = p;
        g_Nv[tid] = n;
    }
    if (tid == 0) cnt = 0;
    __syncthreads();
    if (tid < GG) {
        float p = g_P[tid], n = g_Nv[tid];
        int act0 = 0;
        float sgn = 0.f, rho = 0.f;
        if (n > 0.f) {
            if (p >= 0.f) { act0 = 1; }
            else { act0 = 0; rho = __fdividef(-p, n); sgn = 1.f; }
        } else if (n < 0.f) {
            if (p > 0.f) { act0 = 1; rho = __fdividef(p, -n); sgn = -1.f; }
            else { act0 = 0; }
        } else {
            act0 = (p > 0.f) ? 1 : 0;
        }
        g_act0[tid] = act0;
        if (sgn != 0.f) {
            int e = atomicAdd(&cnt, 1);
            srho[e] = rho; ssg[e] = sgn; sf[e] = tid;
        }
    }
    __syncthreads();
    int E = cnt;
    if (tid == 0) g_nev[0] = E;
    if (tid < E) {
        float r = srho[tid];
        int rank = 0;
        for (int j = 0; j < E; j++) {
            float rj = srho[j];
            rank += (rj < r) || (rj == r && j < tid);
        }
        g_rho[rank]   = r;
        g_esign[rank] = ssg[tid];
        g_ef[rank]    = sf[tid];
    }
}

// ------------------------- setup #2: both transposes + bias -----------------
__global__ void k_trans(const float* __restrict__ W_ih, const float* __restrict__ W_hh,
                        const float* __restrict__ b_ih, const float* __restrict__ b_hh) {
    __shared__ float tle[32][33];
    int x = threadIdx.x, y = threadIdx.y;
    if (blockIdx.y < 63) {
        int f0 = blockIdx.x * 32;
        int h0 = blockIdx.y * 32;
        for (int i = y; i < 32; i += 8) {
            int h = h0 + i, f = f0 + x;
            tle[i][x] = (h < H4 && f < GG) ? W_ih[h * GG + f] : 0.f;
        }
        __syncthreads();
        for (int i = y; i < 32; i += 8) {
            int f = f0 + i, h = h0 + x;
            if (f < GG && h < H4) g_WihT[f * H4 + h] = tle[x][i];
        }
    } else {
        int k0 = blockIdx.x * 32;
        int r0 = (blockIdx.y - 63) * 32;
        for (int i = y; i < 32; i += 8) {
            int r = r0 + i, k = k0 + x;
            tle[i][x] = (r < H4 && k < HH) ? W_hh[r * HH + k] : 0.f;
        }
        __syncthreads();
        for (int i = y; i < 32; i += 8) {
            int k = k0 + i, r = r0 + x;
            if (k < HH && r < H4) {
                int g = r / HH, hc = r % HH;
                g_WX[k * H4P + hc * 4 + g] = tf32r(tle[x][i]);
            }
        }
        if (blockIdx.x == 0 && blockIdx.y == 125) {
            int tid = y * 32 + x;
            for (int h = tid; h < H4; h += 256) {
                int q = (h % HH) * 4 + (h / HH);
                g_bias[q] = b_ih[h] + b_hh[h];
            }
        }
    }
}

// ------------------------- setup #3: tables + front(+seg) + h/c init --------
__global__ void k_prep3(const float* __restrict__ x, const float* __restrict__ Ahat) {
    __shared__ float xr[LL], sp[LL], sn[LL];
    int blk = blockIdx.x;
    int tid = threadIdx.x;
    if (blk < 8) {
        int h = blk * 256 + tid;
        if (h < H4) {
            int q = (h % HH) * 4 + (h / HH);
            float accA = 0.f, accB = 0.f;
            for (int f = 0; f < GG; f++) {
                if (g_act0[f]) {
                    float w = g_WihT[f * H4 + h];
                    accA = fmaf(w, g_P[f],  accA);
                    accB = fmaf(w, g_Nv[f], accB);
                }
            }
            g_Aseg[q] = accA;
            g_Bseg[q] = accB;
            int E = g_nev[0];
            for (int e = 0; e < E; e++) {
                int f = g_ef[e];
                float sgn = g_esign[e];
                float w = g_WihT[f * H4 + h] * sgn;
                accA = fmaf(w, g_P[f],  accA);
                accB = fmaf(w, g_Nv[f], accB);
                g_Aseg[(e + 1) * H4P + q] = accA;
                g_Bseg[(e + 1) * H4P + q] = accB;
            }
        }
    } else {
        int bid = blk - 8;
        int b = bid / TT, t = bid % TT;
        if (tid < LL) xr[tid] = x[(b * TT + t) * LL + tid];
        __syncthreads();
        if (tid < LL) {
            float s = 0.f;
            const float* Ar = &Ahat[tid * LL];
            for (int l = 0; l < LL; l++) s = fmaf(Ar[l], xr[l], s);
            sp[tid] = fmaxf(s, 0.f);
            sn[tid] = fmaxf(-s, 0.f);
        }
        __syncthreads();
        if (tid < LL) {
            float uu = 0.f, vv = 0.f;
            const float* Ar = &Ahat[tid * LL];
            for (int l = 0; l < LL; l++) {
                uu = fmaf(Ar[l], sp[l], uu);
                vv = fmaf(Ar[l], sn[l], vv);
            }
            int n = b * LL + tid;
            int idx = t * NR + n;
            g_u[idx] = uu;
            g_v[idx] = vv;
            int E = g_nev[0];
            int s;
            if (uu > 0.f) {
                float rho = vv / uu;
                int lo = 0, hi = E;
                while (lo < hi) {
                    int mid = (lo + hi) >> 1;
                    if (g_rho[mid] < rho) lo = mid + 1; else hi = mid;
                }
                s = lo;
            } else {
                s = (vv > 0.f) ? E : 0;
            }
            g_seg[idx] = s;
        }
    }
    // zero init h (all KP rows) and c
    int stride = gridDim.x * 256;
    for (int idx = blk * 256 + tid; idx < KP * NR + HH * NR; idx += stride) {
        if (idx < KP * NR) g_hA[idx] = 0.f;
        else               g_c[idx - KP * NR] = 0.f;
    }
}

// ------------------------- fused LSTM step (tf32 mma.sync) ------------------
// grid (16,10): 128 gate-cols x 48 rows per block, 256 threads (8 warps).
// warp owns 16 cols (2 N-frags) x 48 rows (3 M-frags).
__global__ __launch_bounds__(256) void k_step5(int t, int parity) {
    extern __shared__ __align__(16) float sm[];
    const float* hin = parity ? g_hB : g_hA;
    float*      hout = parity ? g_hA : g_hB;
    int tid  = threadIdx.x;
    int warp = tid >> 5;
    int lane = tid & 31;
    int g  = lane >> 2;      // group 0..7
    int tg = lane & 3;       // thread-in-group 0..3
    int bx = blockIdx.x;
    int n0 = blockIdx.y * 48;
    int wc0 = warp * 16;                 // warp col offset inside block tile
    int C0  = bx * 128 + wc0;            // global gate-col base for this warp

    unsigned smbase = (unsigned)__cvta_generic_to_shared(sm);

    auto load_slab = [&](int s, int buf) {
        int k0 = s * KS5;
        unsigned bW = smbase + (unsigned)(buf * SLABF5) * 4u;
        unsigned bH = bW + KS5 * WPAD * 4u;
        #pragma unroll 1
        for (int e = tid; e < KS5 * 32; e += 256) {
            int kk = e >> 5, q = e & 31;
            cp16(bW + (unsigned)(kk * WPAD + q * 4) * 4u,
                 &g_WX[(k0 + kk) * H4P + bx * 128 + q * 4]);
        }
        #pragma unroll 1
        for (int e = tid; e < KS5 * 12; e += 256) {
            int kk = e / 12, q = e - kk * 12;
            cp16(bH + (unsigned)(kk * HPAD + q * 4) * 4u,
                 &hin[(k0 + kk) * NR + n0 + q * 4]);
        }
        cp_commit();
    };

    load_slab(0, 0);

    // prologue: accumulators = u*Aseg[s] + v*Bseg[s] + bias (exact fp32)
    float d[3][2][4];
    {
        int cA0 = C0 + 2 * tg;
        float2 bi0 = *(const float2*)&g_bias[cA0];
        float2 bi1 = *(const float2*)&g_bias[cA0 + 8];
        #pragma unroll
        for (int mi = 0; mi < 3; mi++) {
            int rA = n0 + mi * 16 + g;
            int rB = rA + 8;
            int pA = t * NR + rA, pB = t * NR + rB;
            float uA = g_u[pA], vA = g_v[pA];
            float uB = g_u[pB], vB = g_v[pB];
            int sA = g_seg[pA], sB = g_seg[pB];
            #pragma unroll
            for (int ni = 0; ni < 2; ni++) {
                int c = cA0 + ni * 8;
                float2 bi = ni ? bi1 : bi0;
                float2 aA = *(const float2*)&g_Aseg[sA * H4P + c];
                float2 bA = *(const float2*)&g_Bseg[sA * H4P + c];
                float2 aB = *(const float2*)&g_Aseg[sB * H4P + c];
                float2 bB = *(const float2*)&g_Bseg[sB * H4P + c];
                d[mi][ni][0] = fmaf(uA, aA.x, fmaf(vA, bA.x, bi.x));
                d[mi][ni][1] = fmaf(uA, aA.y, fmaf(vA, bA.y, bi.y));
                d[mi][ni][2] = fmaf(uB, aB.x, fmaf(vB, bB.x, bi.x));
                d[mi][ni][3] = fmaf(uB, aB.y, fmaf(vB, bB.y, bi.y));
            }
        }
    }

    // main loop over K slabs
    #pragma unroll 1
    for (int s = 0; s < NSLAB5; s++) {
        int buf = s & 1;
        if (s + 1 < NSLAB5) {
            load_slab(s + 1, buf ^ 1);
            cp_wait<1>();
        } else {
            cp_wait<0>();
        }
        __syncthreads();
        const float* Wb = sm + buf * SLABF5;
        const float* Hb = Wb + KS5 * WPAD;
        #pragma unroll 2
        for (int c8 = 0; c8 < KS5 / 8; c8++) {
            int kc = c8 * 8;
            unsigned a[3][4], b[2][2];
            #pragma unroll
            for (int mi = 0; mi < 3; mi++) {
                int m = mi * 16 + g;
                a[mi][0] = __float_as_uint(Hb[(kc + tg) * HPAD + m]);
                a[mi][1] = __float_as_uint(Hb[(kc + tg) * HPAD + m + 8]);
                a[mi][2] = __float_as_uint(Hb[(kc + tg + 4) * HPAD + m]);
                a[mi][3] = __float_as_uint(Hb[(kc + tg + 4) * HPAD + m + 8]);
            }
            #pragma unroll
            for (int ni = 0; ni < 2; ni++) {
                int nf = wc0 + ni * 8 + g;
                b[ni][0] = __float_as_uint(Wb[(kc + tg) * WPAD + nf]);
                b[ni][1] = __float_as_uint(Wb[(kc + tg + 4) * WPAD + nf]);
            }
            #pragma unroll
            for (int mi = 0; mi < 3; mi++)
                #pragma unroll
                for (int ni = 0; ni < 2; ni++)
                    mma8(d[mi][ni], a[mi], b[ni]);
        }
        __syncthreads();
    }

    // epilogue: exchange gate pairs, even lanes do LSTM pointwise
    #pragma unroll
    for (int mi = 0; mi < 3; mi++) {
        #pragma unroll
        for (int ni = 0; ni < 2; ni++) {
            float d0 = d[mi][ni][0], d1 = d[mi][ni][1];
            float d2 = d[mi][ni][2], d3 = d[mi][ni][3];
            float e0 = __shfl_xor_sync(0xffffffffu, d0, 1);
            float e1 = __shfl_xor_sync(0xffffffffu, d1, 1);
            float e2 = __shfl_xor_sync(0xffffffffu, d2, 1);
            float e3 = __shfl_xor_sync(0xffffffffu, d3, 1);
            if ((lane & 1) == 0) {
                int c0 = C0 + ni * 8 + 2 * tg;   // gate col of (i,f)
                int hc = c0 >> 2;
                if (hc < HH) {
                    int rA = n0 + mi * 16 + g;
                    int rB = rA + 8;
                    // row A: i=d0 f=d1 g=e0 o=e1
                    float cA = g_c[hc * NR + rA];
                    float ig = fsig(d0), fg = fsig(d1), gg = ftanh(e0), og = fsig(e1);
                    float cn = fmaf(fg, cA, ig * gg);
                    g_c[hc * NR + rA] = cn;
                    hout[hc * NR + rA] = tf32r(og * ftanh(cn));
                    // row B: i=d2 f=d3 g=e2 o=e3
                    float cB = g_c[hc * NR + rB];
                    ig = fsig(d2); fg = fsig(d3); gg = ftanh(e2); og = fsig(e3);
                    cn = fmaf(fg, cB, ig * gg);
                    g_c[hc * NR + rB] = cn;
                    hout[hc * NR + rB] = tf32r(og * ftanh(cn));
                }
            }
        }
    }
}

// ------------------------- transpose h_last to row-major -------------------------
__global__ void k_trh() {
    int idx = blockIdx.x * 256 + threadIdx.x;
    if (idx >= NR * HH) return;
    int n = idx / HH, k = idx % HH;
    g_hT[idx] = g_hA[k * NR + n];   // t=191 (odd parity) wrote into g_hA
}

// ------------------------- generic tiled GEMM: C = act(A @ W + b) -------------------------
__device__ __forceinline__ float* selbuf(int s) {
    switch (s) {
        case 0: return g_hT;
        case 1: return g_z1;
        case 2: return g_z2;
        default: return g_z3;
    }
}

__global__ __launch_bounds__(256) void k_gemm(int aSel, const float* __restrict__ W,
                                              const float* __restrict__ bias, int cSel,
                                              int M, int K, int Nn, int doRelu) {
    const float* A = selbuf(aSel);
    float* C = selbuf(cSel);
    __shared__ __align__(16) float As[16][68];
    __shared__ __align__(16) float Wsm[16][64];
    int tid = threadIdx.x;
    int n0 = blockIdx.x * 64, m0 = blockIdx.y * 64;
    int ty = tid / 16, tx = tid % 16;
    float acc[4][4];
    #pragma unroll
    for (int i = 0; i < 4; i++)
        #pragma unroll
        for (int j = 0; j < 4; j++) acc[i][j] = 0.f;

    for (int k0 = 0; k0 < K; k0 += 16) {
        {
            int mi = tid >> 2;
            int kq = tid & 3;
            int m = m0 + mi;
            #pragma unroll
            for (int j = 0; j < 4; j++) {
                int k = k0 + kq * 4 + j;
                As[kq * 4 + j][mi] = (m < M && k < K) ? A[m * K + k] : 0.f;
            }
        }
        {
            int kk = tid >> 6;
            int nn = tid & 63;
            int n = n0 + nn;
            #pragma unroll
            for (int j = 0; j < 4; j++) {
                int k = k0 + kk + j * 4;
                Wsm[kk + j * 4][nn] = (k < K && n < Nn) ? W[k * Nn + n] : 0.f;
            }
        }
        __syncthreads();
        #pragma unroll
        for (int kk = 0; kk < 16; kk++) {
            float4 a4 = *(const float4*)&As[kk][ty * 4];
            float4 b4 = *(const float4*)&Wsm[kk][tx * 4];
            acc[0][0] = fmaf(a4.x, b4.x, acc[0][0]);
            acc[0][1] = fmaf(a4.x, b4.y, acc[0][1]);
            acc[0][2] = fmaf(a4.x, b4.z, acc[0][2]);
            acc[0][3] = fmaf(a4.x, b4.w, acc[0][3]);
            acc[1][0] = fmaf(a4.y, b4.x, acc[1][0]);
            acc[1][1] = fmaf(a4.y, b4.y, acc[1][1]);
            acc[1][2] = fmaf(a4.y, b4.z, acc[1][2]);
            acc[1][3] = fmaf(a4.y, b4.w, acc[1][3]);
            acc[2][0] = fmaf(a4.z, b4.x, acc[2][0]);
            acc[2][1] = fmaf(a4.z, b4.y, acc[2][1]);
            acc[2][2] = fmaf(a4.z, b4.z, acc[2][2]);
            acc[2][3] = fmaf(a4.z, b4.w, acc[2][3]);
            acc[3][0] = fmaf(a4.w, b4.x, acc[3][0]);
            acc[3][1] = fmaf(a4.w, b4.y, acc[3][1]);
            acc[3][2] = fmaf(a4.w, b4.z, acc[3][2]);
            acc[3][3] = fmaf(a4.w, b4.w, acc[3][3]);
        }
        __syncthreads();
    }

    #pragma unroll
    for (int i = 0; i < 4; i++) {
        int m = m0 + ty * 4 + i;
        if (m >= M) continue;
        #pragma unroll
        for (int j = 0; j < 4; j++) {
            int n = n0 + tx * 4 + j;
            if (n >= Nn) continue;
            float v = acc[i][j] + bias[n];
            if (doRelu) v = fmaxf(v, 0.f);
            C[m * Nn + n] = v;
        }
    }
}

// ------------------------- final layer -------------------------
__global__ void k_final(const float* __restrict__ Wh4, const float* __restrict__ bh4,
                        float* __restrict__ out) {
    __shared__ float zs[M1];
    int n = blockIdx.x;
    int tid = threadIdx.x;
    for (int k = tid; k < M1; k += 256) zs[k] = g_z3[n * M1 + k];
    __syncthreads();
    int w = tid >> 5, lane = tid & 31;
    #pragma unroll
    for (int oi = 0; oi < 3; oi++) {
        int o = w + oi * 8;
        float p = 0.f;
        for (int k = lane; k < M1; k += 32) p = fmaf(zs[k], Wh4[k * OD + o], p);
        #pragma unroll
        for (int off = 16; off; off >>= 1) p += __shfl_down_sync(0xffffffffu, p, off);
        if (lane == 0) {
            float y = fsig(p + bh4[o]);
            int b = n / LL, l = n % LL;
            out[(b * OD + o) * LL + l] = y;
        }
    }
}

// ------------------------- launcher -------------------------
extern "C" void kernel_launch(void* const* d_in, const int* in_sizes, int n_in,
                              void* d_out, int out_size) {
    const float* x    = (const float*)d_in[0];
    const float* Ahat = (const float*)d_in[1];
    const float* W1   = (const float*)d_in[2];
    const float* W2   = (const float*)d_in[3];
    const float* W_ih = (const float*)d_in[4];
    const float* W_hh = (const float*)d_in[5];
    const float* b_ih = (const float*)d_in[6];
    const float* b_hh = (const float*)d_in[7];
    const float* Wh1  = (const float*)d_in[8];
    const float* bh1  = (const float*)d_in[9];
    const float* Wh2  = (const float*)d_in[10];
    const float* bh2  = (const float*)d_in[11];
    const float* Wh3  = (const float*)d_in[12];
    const float* bh3  = (const float*)d_in[13];
    const float* Wh4  = (const float*)d_in[14];
    const float* bh4  = (const float*)d_in[15];
    float* out = (float*)d_out;

    cudaFuncSetAttribute(k_step5, cudaFuncAttributeMaxDynamicSharedMemorySize, SMEM_STEP);

    // exactly 3 setup launches so k_step5(t=0) is launch #4 (ncu target)
    k_setup1<<<1, 512>>>(W1, W2);
    k_trans<<<dim3(16, 126), dim3(32, 8)>>>(W_ih, W_hh, b_ih, b_hh);
    k_prep3<<<8 + BB * TT, 256>>>(x, Ahat);

    dim3 sgrid(16, 10);
    for (int t = 0; t < TT; t++) {
        k_step5<<<sgrid, 256, SMEM_STEP>>>(t, t & 1);
    }

    k_trh<<<(NR * HH + 255) / 256, 256>>>();

    k_gemm<<<dim3((M1 + 63) / 64, (NR + 63) / 64), 256>>>(0, Wh1, bh1, 1, NR, HH, M1, 1);
    k_gemm<<<dim3((M2 + 63) / 64, (NR + 63) / 64), 256>>>(1, Wh2, bh2, 2, NR, M1, M2, 1);
    k_gemm<<<dim3((M1 + 63) / 64, (NR + 63) / 64), 256>>>(2, Wh3, bh3, 3, NR, M2, M1, 1);
    k_final<<<NR, 256>>>(Wh4, bh4, out);
}

// round 7
// speedup vs baseline: 5.3134x; 1.3541x over previous
#include <cuda_runtime.h>
#include <cuda_bf16.h>
#include <math.h>

#define BB 4
#define TT 192
#define LL 120
#define GG 500
#define HH 500      // HL
#define H4 2000
#define H4P 2048    // padded gate-col count
#define KP 512      // padded K
#define NR 480      // B*L
#define OD 24
#define M1 3000
#define M2 1000

// step kernel tiling (bf16)
#define KS6 64
#define NSLAB6 (KP / KS6)                 // 8
#define WSTR 36                           // u32 stride per col/row (32 data + 4 pad)
#define SLAB6U (128*WSTR + 48*WSTR)       // 6336 u32 per slab buffer
#define SMEM6 (3 * SLAB6U * 4)            // 76032 B (3-stage pipeline)

// ------------------------- scratch (device globals) -------------------------
__device__ float g_P[GG];
__device__ float g_Nv[GG];
__device__ float g_rho[GG];
__device__ float g_esign[GG];
__device__ int   g_ef[GG];
__device__ int   g_act0[GG];
__device__ int   g_nev[1];
__device__ __align__(16) float g_bias[H4P];              // interleaved hc*4+gate
__device__ __align__(16) float g_Aseg[(GG + 1) * H4P];   // interleaved
__device__ __align__(16) float g_Bseg[(GG + 1) * H4P];   // interleaved
__device__ __align__(16) float g_WihT[GG * H4];          // [f][h] (orig order)
__device__ __align__(16) unsigned short g_WXh[H4P * KP]; // bf16 W_hh, [col][k]
__device__ __align__(16) float g_u[TT * NR];
__device__ __align__(16) float g_v[TT * NR];
__device__ __align__(16) int   g_seg[TT * NR];
__device__ __align__(16) unsigned short g_hA16[NR * KP]; // bf16 h, [row][k]
__device__ __align__(16) unsigned short g_hB16[NR * KP];
__device__ __align__(16) float g_c[HH * NR];             // c fp32, k-major
__device__ __align__(16) float g_hF[HH * NR];            // fp32 h_last, k-major
__device__ __align__(16) float g_hT[NR * HH];
__device__ __align__(16) float g_z1[NR * M1];
__device__ __align__(16) float g_z2[NR * M2];
__device__ __align__(16) float g_z3[NR * M1];

// ------------------------- math helpers -------------------------
__device__ __forceinline__ float fsig(float x) {
    return __fdividef(1.f, 1.f + __expf(-x));
}
__device__ __forceinline__ float ftanh(float x) {
    float ax = fabsf(x);
    float t  = __expf(-2.f * ax);
    float r  = __fdividef(1.f - t, 1.f + t);
    return copysignf(r, x);
}
__device__ __forceinline__ float tf32r(float x) {
    unsigned r;
    asm("cvt.rna.tf32.f32 %0, %1;" : "=r"(r) : "f"(x));
    return __uint_as_float(r);
}
__device__ __forceinline__ unsigned short f2bf(float v) {
    __nv_bfloat16 b = __float2bfloat16_rn(v);
    return *reinterpret_cast<unsigned short*>(&b);
}

__device__ __forceinline__ void cp16(unsigned dst_smem, const void* src) {
    asm volatile("cp.async.cg.shared.global [%0], [%1], 16;" :: "r"(dst_smem), "l"(src));
}
__device__ __forceinline__ void cp_commit() {
    asm volatile("cp.async.commit_group;");
}
template <int N>
__device__ __forceinline__ void cp_wait() {
    asm volatile("cp.async.wait_group %0;" :: "n"(N));
}

// bf16 m16n8k16 MMA (fp32 accumulate)
__device__ __forceinline__ void mma16bf(float* d, const unsigned* a, const unsigned* b) {
    asm volatile(
        "mma.sync.aligned.m16n8k16.row.col.f32.bf16.bf16.f32 "
        "{%0,%1,%2,%3}, {%4,%5,%6,%7}, {%8,%9}, {%0,%1,%2,%3};"
        : "+f"(d[0]), "+f"(d[1]), "+f"(d[2]), "+f"(d[3])
        : "r"(a[0]), "r"(a[1]), "r"(a[2]), "r"(a[3]), "r"(b[0]), "r"(b[1]));
}
// tf32 m16n8k8 MMA (fp32 accumulate)
__device__ __forceinline__ void mma8(float* d, const unsigned* a, const unsigned* b) {
    asm volatile(
        "mma.sync.aligned.m16n8k8.row.col.f32.tf32.tf32.f32 "
        "{%0,%1,%2,%3}, {%4,%5,%6,%7}, {%8,%9}, {%0,%1,%2,%3};"
        : "+f"(d[0]), "+f"(d[1]), "+f"(d[2]), "+f"(d[3])
        : "r"(a[0]), "r"(a[1]), "r"(a[2]), "r"(a[3]), "r"(b[0]), "r"(b[1]));
}

// ------------------------- setup #1: P,N + breakpoint events (1 block) ------
__global__ void k_setup1(const float* __restrict__ W1, const float* __restrict__ W2) {
    __shared__ float srho[GG];
    __shared__ float ssg[GG];
    __shared__ int   sf[GG];
    __shared__ int   cnt;
    int tid = threadIdx.x;
    if (tid < GG) {
        float p = 0.f, n = 0.f;
        for (int g = 0; g < GG; g++) {
            float w = W1[g];
            float v = W2[g * GG + tid];
            p = fmaf(fmaxf(w, 0.f), v, p);
            n = fmaf(fmaxf(-w, 0.f), v, n);
        }
        g_P[tid]  = p;
        g_Nv[tid] = n;
    }
    if (tid == 0) cnt = 0;
    __syncthreads();
    if (tid < GG) {
        float p = g_P[tid], n = g_Nv[tid];
        int act0 = 0;
        float sgn = 0.f, rho = 0.f;
        if (n > 0.f) {
            if (p >= 0.f) { act0 = 1; }
            else { act0 = 0; rho = __fdividef(-p, n); sgn = 1.f; }
        } else if (n < 0.f) {
            if (p > 0.f) { act0 = 1; rho = __fdividef(p, -n); sgn = -1.f; }
            else { act0 = 0; }
        } else {
            act0 = (p > 0.f) ? 1 : 0;
        }
        g_act0[tid] = act0;
        if (sgn != 0.f) {
            int e = atomicAdd(&cnt, 1);
            srho[e] = rho; ssg[e] = sgn; sf[e] = tid;
        }
    }
    __syncthreads();
    int E = cnt;
    if (tid == 0) g_nev[0] = E;
    if (tid < E) {
        float r = srho[tid];
        int rank = 0;
        for (int j = 0; j < E; j++) {
            float rj = srho[j];
            rank += (rj < r) || (rj == r && j < tid);
        }
        g_rho[rank]   = r;
        g_esign[rank] = ssg[tid];
        g_ef[rank]    = sf[tid];
    }
}

// ------------------------- setup #2: both transposes + bias -----------------
__global__ void k_trans(const float* __restrict__ W_ih, const float* __restrict__ W_hh,
                        const float* __restrict__ b_ih, const float* __restrict__ b_hh) {
    __shared__ float tle[32][33];
    int x = threadIdx.x, y = threadIdx.y;
    if (blockIdx.y < 63) {
        int f0 = blockIdx.x * 32;
        int h0 = blockIdx.y * 32;
        for (int i = y; i < 32; i += 8) {
            int h = h0 + i, f = f0 + x;
            tle[i][x] = (h < H4 && f < GG) ? W_ih[h * GG + f] : 0.f;
        }
        __syncthreads();
        for (int i = y; i < 32; i += 8) {
            int f = f0 + i, h = h0 + x;
            if (f < GG && h < H4) g_WihT[f * H4 + h] = tle[x][i];
        }
    } else {
        int k0 = blockIdx.x * 32;
        int r0 = (blockIdx.y - 63) * 32;
        for (int i = y; i < 32; i += 8) {
            int r = r0 + i, k = k0 + x;
            tle[i][x] = (r < H4 && k < HH) ? W_hh[r * HH + k] : 0.f;
        }
        __syncthreads();
        for (int i = y; i < 32; i += 8) {
            int k = k0 + i, r = r0 + x;
            if (k < HH && r < H4) {
                int g = r / HH, hc = r % HH;
                g_WXh[(hc * 4 + g) * KP + k] = f2bf(tle[x][i]);
            }
        }
        if (blockIdx.x == 0 && blockIdx.y == 125) {
            int tid = y * 32 + x;
            for (int h = tid; h < H4; h += 256) {
                int q = (h % HH) * 4 + (h / HH);
                g_bias[q] = b_ih[h] + b_hh[h];
            }
        }
    }
}

// ------------------------- setup #3: tables + front(+seg) + h/c init --------
__global__ void k_prep3(const float* __restrict__ x, const float* __restrict__ Ahat) {
    __shared__ float xr[LL], sp[LL], sn[LL];
    int blk = blockIdx.x;
    int tid = threadIdx.x;
    if (blk < 8) {
        int h = blk * 256 + tid;
        if (h < H4) {
            int q = (h % HH) * 4 + (h / HH);
            float accA = 0.f, accB = 0.f;
            for (int f = 0; f < GG; f++) {
                if (g_act0[f]) {
                    float w = g_WihT[f * H4 + h];
                    accA = fmaf(w, g_P[f],  accA);
                    accB = fmaf(w, g_Nv[f], accB);
                }
            }
            g_Aseg[q] = accA;
            g_Bseg[q] = accB;
            int E = g_nev[0];
            for (int e = 0; e < E; e++) {
                int f = g_ef[e];
                float sgn = g_esign[e];
                float w = g_WihT[f * H4 + h] * sgn;
                accA = fmaf(w, g_P[f],  accA);
                accB = fmaf(w, g_Nv[f], accB);
                g_Aseg[(e + 1) * H4P + q] = accA;
                g_Bseg[(e + 1) * H4P + q] = accB;
            }
        }
    } else {
        int bid = blk - 8;
        int b = bid / TT, t = bid % TT;
        if (tid < LL) xr[tid] = x[(b * TT + t) * LL + tid];
        __syncthreads();
        if (tid < LL) {
            float s = 0.f;
            const float* Ar = &Ahat[tid * LL];
            for (int l = 0; l < LL; l++) s = fmaf(Ar[l], xr[l], s);
            sp[tid] = fmaxf(s, 0.f);
            sn[tid] = fmaxf(-s, 0.f);
        }
        __syncthreads();
        if (tid < LL) {
            float uu = 0.f, vv = 0.f;
            const float* Ar = &Ahat[tid * LL];
            for (int l = 0; l < LL; l++) {
                uu = fmaf(Ar[l], sp[l], uu);
                vv = fmaf(Ar[l], sn[l], vv);
            }
            int n = b * LL + tid;
            int idx = t * NR + n;
            g_u[idx] = uu;
            g_v[idx] = vv;
            int E = g_nev[0];
            int s;
            if (uu > 0.f) {
                float rho = vv / uu;
                int lo = 0, hi = E;
                while (lo < hi) {
                    int mid = (lo + hi) >> 1;
                    if (g_rho[mid] < rho) lo = mid + 1; else hi = mid;
                }
                s = lo;
            } else {
                s = (vv > 0.f) ? E : 0;
            }
            g_seg[idx] = s;
        }
    }
    // zero h0 (bf16, as u32) and c (fp32)
    const int HA_U = NR * KP / 2;              // u32 slots in g_hA16
    int stride = gridDim.x * 256;
    for (int idx = blk * 256 + tid; idx < HA_U + HH * NR; idx += stride) {
        if (idx < HA_U) reinterpret_cast<unsigned*>(g_hA16)[idx] = 0u;
        else            g_c[idx - HA_U] = 0.f;
    }
}

// ------------------------- fused LSTM step (bf16 m16n8k16) ------------------
// grid (16,10): 128 gate-cols x 48 rows per block, 256 threads (8 warps).
// warp owns 16 cols (2 n-frags) x 48 rows (3 m-frags).
__global__ __launch_bounds__(256) void k_step6(int t, int parity) {
    extern __shared__ __align__(16) float smf[];
    unsigned* sm = reinterpret_cast<unsigned*>(smf);
    const unsigned short* hin = parity ? g_hB16 : g_hA16;
    unsigned short*      hout = parity ? g_hA16 : g_hB16;
    int tid  = threadIdx.x;
    int warp = tid >> 5;
    int lane = tid & 31;
    int g  = lane >> 2;
    int tg = lane & 3;
    int bx = blockIdx.x;
    int n0 = blockIdx.y * 48;
    int wc0 = warp * 16;
    int C0  = bx * 128 + wc0;

    unsigned smbase = (unsigned)__cvta_generic_to_shared(smf);

    auto load_slab = [&](int s, int buf) {
        int k0 = s * KS6;
        unsigned bW = smbase + (unsigned)(buf * SLAB6U) * 4u;
        unsigned bH = bW + 128u * WSTR * 4u;
        // W: 128 cols x 64 bf16 = 1024 cp16
        #pragma unroll 1
        for (int e = tid; e < 128 * 8; e += 256) {
            int col = e >> 3, q = e & 7;
            cp16(bW + (unsigned)(col * WSTR + q * 4) * 4u,
                 (const char*)g_WXh + ((size_t)(bx * 128 + col) * KP + k0 + q * 8) * 2);
        }
        // H: 48 rows x 64 bf16 = 384 cp16
        #pragma unroll 1
        for (int e = tid; e < 48 * 8; e += 256) {
            int row = e >> 3, q = e & 7;
            cp16(bH + (unsigned)(row * WSTR + q * 4) * 4u,
                 (const char*)hin + ((size_t)(n0 + row) * KP + k0 + q * 8) * 2);
        }
        cp_commit();
    };

    load_slab(0, 0);
    load_slab(1, 1);

    // prologue: accumulators = u*Aseg[s] + v*Bseg[s] + bias (exact fp32)
    float d[3][2][4];
    {
        int cA0 = C0 + 2 * tg;
        float2 bi0 = *(const float2*)&g_bias[cA0];
        float2 bi1 = *(const float2*)&g_bias[cA0 + 8];
        #pragma unroll
        for (int mi = 0; mi < 3; mi++) {
            int rA = n0 + mi * 16 + g;
            int rB = rA + 8;
            int pA = t * NR + rA, pB = t * NR + rB;
            float uA = g_u[pA], vA = g_v[pA];
            float uB = g_u[pB], vB = g_v[pB];
            int sA = g_seg[pA], sB = g_seg[pB];
            #pragma unroll
            for (int ni = 0; ni < 2; ni++) {
                int c = cA0 + ni * 8;
                float2 bi = ni ? bi1 : bi0;
                float2 aA = *(const float2*)&g_Aseg[sA * H4P + c];
                float2 bA = *(const float2*)&g_Bseg[sA * H4P + c];
                float2 aB = *(const float2*)&g_Aseg[sB * H4P + c];
                float2 bB = *(const float2*)&g_Bseg[sB * H4P + c];
                d[mi][ni][0] = fmaf(uA, aA.x, fmaf(vA, bA.x, bi.x));
                d[mi][ni][1] = fmaf(uA, aA.y, fmaf(vA, bA.y, bi.y));
                d[mi][ni][2] = fmaf(uB, aB.x, fmaf(vB, bB.x, bi.x));
                d[mi][ni][3] = fmaf(uB, aB.y, fmaf(vB, bB.y, bi.y));
            }
        }
    }

    // main loop: 8 slabs of K=64 (4 k16 chunks each), 3-stage pipeline
    #pragma unroll 1
    for (int s = 0; s < NSLAB6; s++) {
        int buf = s % 3;
        if (s + 2 < NSLAB6) {
            load_slab(s + 2, (s + 2) % 3);
            cp_wait<2>();
        } else if (s + 1 < NSLAB6) {
            cp_wait<1>();
        } else {
            cp_wait<0>();
        }
        __syncthreads();
        const unsigned* Wb = sm + buf * SLAB6U;
        const unsigned* Hb = Wb + 128 * WSTR;
        #pragma unroll
        for (int c16 = 0; c16 < KS6 / 16; c16++) {
            int kc = c16 * 8;   // u32 offset within row
            unsigned a[3][4], b[2][2];
            #pragma unroll
            for (int mi = 0; mi < 3; mi++) {
                int base = (mi * 16 + g) * WSTR + kc + tg;
                a[mi][0] = Hb[base];
                a[mi][1] = Hb[base + 8 * WSTR];
                a[mi][2] = Hb[base + 4];
                a[mi][3] = Hb[base + 8 * WSTR + 4];
            }
            #pragma unroll
            for (int ni = 0; ni < 2; ni++) {
                int wb = (wc0 + ni * 8 + g) * WSTR + kc + tg;
                b[ni][0] = Wb[wb];
                b[ni][1] = Wb[wb + 4];
            }
            #pragma unroll
            for (int mi = 0; mi < 3; mi++)
                #pragma unroll
                for (int ni = 0; ni < 2; ni++)
                    mma16bf(d[mi][ni], a[mi], b[ni]);
        }
        __syncthreads();
    }

    // epilogue: exchange gate pairs, even lanes do LSTM pointwise
    int last = (t == TT - 1);
    #pragma unroll
    for (int mi = 0; mi < 3; mi++) {
        #pragma unroll
        for (int ni = 0; ni < 2; ni++) {
            float d0 = d[mi][ni][0], d1 = d[mi][ni][1];
            float d2 = d[mi][ni][2], d3 = d[mi][ni][3];
            float e0 = __shfl_xor_sync(0xffffffffu, d0, 1);
            float e1 = __shfl_xor_sync(0xffffffffu, d1, 1);
            float e2 = __shfl_xor_sync(0xffffffffu, d2, 1);
            float e3 = __shfl_xor_sync(0xffffffffu, d3, 1);
            if ((lane & 1) == 0) {
                int c0 = C0 + ni * 8 + 2 * tg;   // gate col of (i,f)
                int hc = c0 >> 2;
                if (hc < HH) {
                    int rA = n0 + mi * 16 + g;
                    int rB = rA + 8;
                    // row A: i=d0 f=d1 g=e0 o=e1
                    float cA = g_c[hc * NR + rA];
                    float ig = fsig(d0), fg = fsig(d1), gg = ftanh(e0), og = fsig(e1);
                    float cn = fmaf(fg, cA, ig * gg);
                    g_c[hc * NR + rA] = cn;
                    float hv = og * ftanh(cn);
                    hout[(size_t)rA * KP + hc] = f2bf(hv);
                    if (last) g_hF[hc * NR + rA] = hv;
                    // row B
                    float cB = g_c[hc * NR + rB];
                    ig = fsig(d2); fg = fsig(d3); gg = ftanh(e2); og = fsig(e3);
                    cn = fmaf(fg, cB, ig * gg);
                    g_c[hc * NR + rB] = cn;
                    hv = og * ftanh(cn);
                    hout[(size_t)rB * KP + hc] = f2bf(hv);
                    if (last) g_hF[hc * NR + rB] = hv;
                }
            }
        }
    }
}

// ------------------------- transpose h_last to row-major -------------------------
__global__ void k_trh() {
    int idx = blockIdx.x * 256 + threadIdx.x;
    if (idx >= NR * HH) return;
    int n = idx / HH, k = idx % HH;
    g_hT[idx] = g_hF[k * NR + n];
}

// ------------------------- tf32 MMA GEMM: C = act(A @ W + b) ----------------
__device__ __forceinline__ float* selbuf(int s) {
    switch (s) {
        case 0: return g_hT;
        case 1: return g_z1;
        case 2: return g_z2;
        default: return g_z3;
    }
}

// block: 256 thr (8 warps), tile M64 x N64, KS=32. warp = 32m x 16n.
__global__ __launch_bounds__(256) void k_gemmt(int aSel, const float* __restrict__ W,
                                               const float* __restrict__ bias, int cSel,
                                               int M, int K, int N, int doRelu) {
    const float* A = selbuf(aSel);
    float* C = selbuf(cSel);
    __shared__ __align__(16) float As[64 * 36];   // [m][k], stride 36
    __shared__ __align__(16) float Ws[32 * 72];   // [k][n], stride 72
    int tid  = threadIdx.x;
    int warp = tid >> 5;
    int lane = tid & 31;
    int g  = lane >> 2;
    int tg = lane & 3;
    int n0 = blockIdx.x * 64, m0 = blockIdx.y * 64;
    int wm = (warp >> 2) * 32;   // warp m offset
    int wn = (warp & 3) * 16;    // warp n offset

    // reg staging indices
    int ami = tid >> 2;            // 0..63 (A row)
    int akq = (tid & 3) * 8;       // A k offset
    int wkk = tid >> 3;            // 0..31 (W k row)
    int wnq = (tid & 7) * 8;       // W n offset

    float d[2][2][4];
    #pragma unroll
    for (int i = 0; i < 2; i++)
        #pragma unroll
        for (int j = 0; j < 2; j++)
            #pragma unroll
            for (int q = 0; q < 4; q++) d[i][j][q] = 0.f;

    int nslab = (K + 31) / 32;
    float rA[8], rW[8];

    // prefetch slab 0
    {
        int m = m0 + ami;
        #pragma unroll
        for (int j = 0; j < 8; j++) {
            int k = akq + j;
            rA[j] = (m < M && k < K) ? A[(size_t)m * K + k] : 0.f;
        }
        #pragma unroll
        for (int j = 0; j < 8; j++) {
            int n = n0 + wnq + j;
            rW[j] = (wkk < K && n < N) ? W[(size_t)wkk * N + n] : 0.f;
        }
    }

    #pragma unroll 1
    for (int s = 0; s < nslab; s++) {
        // store staged regs (tf32-rounded)
        #pragma unroll
        for (int j = 0; j < 8; j++) As[ami * 36 + akq + j] = tf32r(rA[j]);
        #pragma unroll
        for (int j = 0; j < 8; j++) Ws[wkk * 72 + wnq + j] = tf32r(rW[j]);
        __syncthreads();
        // prefetch next slab
        if (s + 1 < nslab) {
            int k0 = (s + 1) * 32;
            int m = m0 + ami;
            #pragma unroll
            for (int j = 0; j < 8; j++) {
                int k = k0 + akq + j;
                rA[j] = (m < M && k < K) ? A[(size_t)m * K + k] : 0.f;
            }
            #pragma unroll
            for (int j = 0; j < 8; j++) {
                int k = k0 + wkk;
                int n = n0 + wnq + j;
                rW[j] = (k < K && n < N) ? W[(size_t)k * N + n] : 0.f;
            }
        }
        // compute 4 k8 chunks
        const unsigned* Asu = reinterpret_cast<const unsigned*>(As);
        const unsigned* Wsu = reinterpret_cast<const unsigned*>(Ws);
        #pragma unroll
        for (int c8 = 0; c8 < 4; c8++) {
            int kc = c8 * 8;
            unsigned a[2][4], b[2][2];
            #pragma unroll
            for (int mi = 0; mi < 2; mi++) {
                int mbase = (wm + mi * 16 + g) * 36 + kc;
                a[mi][0] = Asu[mbase + tg];
                a[mi][1] = Asu[mbase + 8 * 36 + tg];
                a[mi][2] = Asu[mbase + tg + 4];
                a[mi][3] = Asu[mbase + 8 * 36 + tg + 4];
            }
            #pragma unroll
            for (int ni = 0; ni < 2; ni++) {
                int nb = wn + ni * 8 + g;
                b[ni][0] = Wsu[(kc + tg) * 72 + nb];
                b[ni][1] = Wsu[(kc + tg + 4) * 72 + nb];
            }
            #pragma unroll
            for (int mi = 0; mi < 2; mi++)
                #pragma unroll
                for (int ni = 0; ni < 2; ni++)
                    mma8(d[mi][ni], a[mi], b[ni]);
        }
        __syncthreads();
    }

    // epilogue: rows m = m0+wm+mi*16+g (+8); cols n = n0+wn+ni*8+2tg (+1)
    #pragma unroll
    for (int mi = 0; mi < 2; mi++) {
        #pragma unroll
        for (int ni = 0; ni < 2; ni++) {
            int mA = m0 + wm + mi * 16 + g;
            int mB = mA + 8;
            int n  = n0 + wn + ni * 8 + 2 * tg;
            float b0 = (n < N)     ? bias[n]     : 0.f;
            float b1 = (n + 1 < N) ? bias[n + 1] : 0.f;
            float v;
            if (mA < M) {
                if (n < N) {
                    v = d[mi][ni][0] + b0;
                    C[(size_t)mA * N + n] = doRelu ? fmaxf(v, 0.f) : v;
                }
                if (n + 1 < N) {
                    v = d[mi][ni][1] + b1;
                    C[(size_t)mA * N + n + 1] = doRelu ? fmaxf(v, 0.f) : v;
                }
            }
            if (mB < M) {
                if (n < N) {
                    v = d[mi][ni][2] + b0;
                    C[(size_t)mB * N + n] = doRelu ? fmaxf(v, 0.f) : v;
                }
                if (n + 1 < N) {
                    v = d[mi][ni][3] + b1;
                    C[(size_t)mB * N + n + 1] = doRelu ? fmaxf(v, 0.f) : v;
                }
            }
        }
    }
}

// ------------------------- final layer -------------------------
__global__ void k_final(const float* __restrict__ Wh4, const float* __restrict__ bh4,
                        float* __restrict__ out) {
    __shared__ float zs[M1];
    int n = blockIdx.x;
    int tid = threadIdx.x;
    for (int k = tid; k < M1; k += 256) zs[k] = g_z3[n * M1 + k];
    __syncthreads();
    int w = tid >> 5, lane = tid & 31;
    #pragma unroll
    for (int oi = 0; oi < 3; oi++) {
        int o = w + oi * 8;
        float p = 0.f;
        for (int k = lane; k < M1; k += 32) p = fmaf(zs[k], Wh4[k * OD + o], p);
        #pragma unroll
        for (int off = 16; off; off >>= 1) p += __shfl_down_sync(0xffffffffu, p, off);
        if (lane == 0) {
            float y = fsig(p + bh4[o]);
            int b = n / LL, l = n % LL;
            out[(b * OD + o) * LL + l] = y;
        }
    }
}

// ------------------------- launcher -------------------------
extern "C" void kernel_launch(void* const* d_in, const int* in_sizes, int n_in,
                              void* d_out, int out_size) {
    const float* x    = (const float*)d_in[0];
    const float* Ahat = (const float*)d_in[1];
    const float* W1   = (const float*)d_in[2];
    const float* W2   = (const float*)d_in[3];
    const float* W_ih = (const float*)d_in[4];
    const float* W_hh = (const float*)d_in[5];
    const float* b_ih = (const float*)d_in[6];
    const float* b_hh = (const float*)d_in[7];
    const float* Wh1  = (const float*)d_in[8];
    const float* bh1  = (const float*)d_in[9];
    const float* Wh2  = (const float*)d_in[10];
    const float* bh2  = (const float*)d_in[11];
    const float* Wh3  = (const float*)d_in[12];
    const float* bh3  = (const float*)d_in[13];
    const float* Wh4  = (const float*)d_in[14];
    const float* bh4  = (const float*)d_in[15];
    float* out = (float*)d_out;

    cudaFuncSetAttribute(k_step6, cudaFuncAttributeMaxDynamicSharedMemorySize, SMEM6);

    // exactly 3 setup launches so k_step6(t=0) is launch #4 (ncu target)
    k_setup1<<<1, 512>>>(W1, W2);
    k_trans<<<dim3(16, 126), dim3(32, 8)>>>(W_ih, W_hh, b_ih, b_hh);
    k_prep3<<<8 + BB * TT, 256>>>(x, Ahat);

    dim3 sgrid(16, 10);
    for (int t = 0; t < TT; t++) {
        k_step6<<<sgrid, 256, SMEM6>>>(t, t & 1);
    }

    k_trh<<<(NR * HH + 255) / 256, 256>>>();

    // z1 = relu(hT @ Wh1 + bh1)   [480 x 3000], K=500
    k_gemmt<<<dim3(47, 8), 256>>>(0, Wh1, bh1, 1, NR, HH, M1, 1);
    // z2 = relu(z1 @ Wh2 + bh2)   [480 x 1000], K=3000
    k_gemmt<<<dim3(16, 8), 256>>>(1, Wh2, bh2, 2, NR, M1, M2, 1);
    // z3 = relu(z2 @ Wh3 + bh3)   [480 x 3000], K=1000
    k_gemmt<<<dim3(47, 8), 256>>>(2, Wh3, bh3, 3, NR, M2, M1, 1);
    // y = sigmoid(z3 @ Wh4 + bh4) -> out[b][o][l]
    k_final<<<NR, 256>>>(Wh4, bh4, out);
}

// round 8
// speedup vs baseline: 6.3608x; 1.1971x over previous
#include <cuda_runtime.h>
#include <cuda_bf16.h>
#include <math.h>

#define BB 4
#define TT 192
#define LL 120
#define GG 500
#define HH 500      // HL
#define H4 2000
#define H4P 2048    // padded gate-col count
#define KP 512      // padded K
#define NR 480      // B*L
#define NRP 512     // padded rows
#define OD 24
#define M1 3000
#define M2 1000

// persistent step kernel tiling
#define GRID7 128                  // 32 col-tiles x 4 row-tiles
#define COLT 64                    // gate-cols per block
#define ROWT 128                   // rows per block
#define WSTRC 520                  // bf16 stride per W col (512 + 8 pad)
#define ASTR 136                   // bf16 stride per A row (128 + 8 pad)
#define SLABK 128                  // k per A slab
#define ABUF (ROWT * ASTR)         // bf16 units per A buffer (17408)
#define SWBYTES (COLT * WSTRC * 2) // 66560
#define SMEM7 (SWBYTES + 2 * ABUF * 2)  // 66560 + 69632 = 136192

// ------------------------- scratch (device globals) -------------------------
__device__ float g_P[GG];
__device__ float g_Nv[GG];
__device__ float g_rho[GG];
__device__ float g_esign[GG];
__device__ int   g_ef[GG];
__device__ int   g_act0[GG];
__device__ int   g_nev[1];
__device__ __align__(16) float g_bias[H4P];              // interleaved hc*4+gate
__device__ __align__(16) float g_Aseg[(GG + 1) * H4P];   // interleaved
__device__ __align__(16) float g_Bseg[(GG + 1) * H4P];   // interleaved
__device__ __align__(16) float g_WihT[GG * H4];          // [f][h] (orig order)
__device__ __align__(16) unsigned short g_WXh[H4P * KP]; // bf16 W_hh, [col][k]
__device__ __align__(16) float g_u[TT * NRP];
__device__ __align__(16) float g_v[TT * NRP];
__device__ __align__(16) int   g_seg[TT * NRP];
__device__ __align__(16) unsigned short g_h3[3][NRP * KP]; // bf16 h ring, [row][k]
__device__ __align__(16) float g_c[HH * NRP];            // c fp32, [hc][row]
__device__ __align__(16) float g_hF[HH * NRP];           // fp32 h_last, [hc][row]
__device__ unsigned g_bar[TT];                           // grid barrier counters
__device__ __align__(16) float g_hT[NR * HH];
__device__ __align__(16) float g_z1[NR * M1];
__device__ __align__(16) float g_z2[NR * M2];
__device__ __align__(16) float g_z3[NR * M1];

// ------------------------- math helpers -------------------------
__device__ __forceinline__ float fsig(float x) {
    return __fdividef(1.f, 1.f + __expf(-x));
}
__device__ __forceinline__ float ftanh(float x) {
    float ax = fabsf(x);
    float t  = __expf(-2.f * ax);
    float r  = __fdividef(1.f - t, 1.f + t);
    return copysignf(r, x);
}
__device__ __forceinline__ float tf32r(float x) {
    unsigned r;
    asm("cvt.rna.tf32.f32 %0, %1;" : "=r"(r) : "f"(x));
    return __uint_as_float(r);
}
__device__ __forceinline__ unsigned short f2bf(float v) {
    __nv_bfloat16 b = __float2bfloat16_rn(v);
    return *reinterpret_cast<unsigned short*>(&b);
}

__device__ __forceinline__ void cp16(unsigned dst_smem, const void* src) {
    asm volatile("cp.async.cg.shared.global [%0], [%1], 16;" :: "r"(dst_smem), "l"(src));
}
__device__ __forceinline__ void cp_commit() {
    asm volatile("cp.async.commit_group;");
}
template <int N>
__device__ __forceinline__ void cp_wait() {
    asm volatile("cp.async.wait_group %0;" :: "n"(N));
}

__device__ __forceinline__ void ldsm4(unsigned* r, unsigned addr) {
    asm volatile("ldmatrix.sync.aligned.m8n8.x4.shared.b16 {%0,%1,%2,%3}, [%4];"
                 : "=r"(r[0]), "=r"(r[1]), "=r"(r[2]), "=r"(r[3]) : "r"(addr));
}

// bf16 m16n8k16 MMA (fp32 accumulate)
__device__ __forceinline__ void mma16bf(float* d, const unsigned* a, const unsigned* b) {
    asm volatile(
        "mma.sync.aligned.m16n8k16.row.col.f32.bf16.bf16.f32 "
        "{%0,%1,%2,%3}, {%4,%5,%6,%7}, {%8,%9}, {%0,%1,%2,%3};"
        : "+f"(d[0]), "+f"(d[1]), "+f"(d[2]), "+f"(d[3])
        : "r"(a[0]), "r"(a[1]), "r"(a[2]), "r"(a[3]), "r"(b[0]), "r"(b[1]));
}
// tf32 m16n8k8 MMA (fp32 accumulate)
__device__ __forceinline__ void mma8(float* d, const unsigned* a, const unsigned* b) {
    asm volatile(
        "mma.sync.aligned.m16n8k8.row.col.f32.tf32.tf32.f32 "
        "{%0,%1,%2,%3}, {%4,%5,%6,%7}, {%8,%9}, {%0,%1,%2,%3};"
        : "+f"(d[0]), "+f"(d[1]), "+f"(d[2]), "+f"(d[3])
        : "r"(a[0]), "r"(a[1]), "r"(a[2]), "r"(a[3]), "r"(b[0]), "r"(b[1]));
}

// ------------------------- setup #1: P,N + breakpoint events (1 block) ------
__global__ void k_setup1(const float* __restrict__ W1, const float* __restrict__ W2) {
    __shared__ float srho[GG];
    __shared__ float ssg[GG];
    __shared__ int   sf[GG];
    __shared__ int   cnt;
    int tid = threadIdx.x;
    if (tid < GG) {
        float p = 0.f, n = 0.f;
        for (int g = 0; g < GG; g++) {
            float w = W1[g];
            float v = W2[g * GG + tid];
            p = fmaf(fmaxf(w, 0.f), v, p);
            n = fmaf(fmaxf(-w, 0.f), v, n);
        }
        g_P[tid]  = p;
        g_Nv[tid] = n;
    }
    if (tid == 0) cnt = 0;
    __syncthreads();
    if (tid < GG) {
        float p = g_P[tid], n = g_Nv[tid];
        int act0 = 0;
        float sgn = 0.f, rho = 0.f;
        if (n > 0.f) {
            if (p >= 0.f) { act0 = 1; }
            else { act0 = 0; rho = __fdividef(-p, n); sgn = 1.f; }
        } else if (n < 0.f) {
            if (p > 0.f) { act0 = 1; rho = __fdividef(p, -n); sgn = -1.f; }
            else { act0 = 0; }
        } else {
            act0 = (p > 0.f) ? 1 : 0;
        }
        g_act0[tid] = act0;
        if (sgn != 0.f) {
            int e = atomicAdd(&cnt, 1);
            srho[e] = rho; ssg[e] = sgn; sf[e] = tid;
        }
    }
    __syncthreads();
    int E = cnt;
    if (tid == 0) g_nev[0] = E;
    if (tid < E) {
        float r = srho[tid];
        int rank = 0;
        for (int j = 0; j < E; j++) {
            float rj = srho[j];
            rank += (rj < r) || (rj == r && j < tid);
        }
        g_rho[rank]   = r;
        g_esign[rank] = ssg[tid];
        g_ef[rank]    = sf[tid];
    }
}

// ------------------------- setup #2: both transposes + bias -----------------
__global__ void k_trans(const float* __restrict__ W_ih, const float* __restrict__ W_hh,
                        const float* __restrict__ b_ih, const float* __restrict__ b_hh) {
    __shared__ float tle[32][33];
    int x = threadIdx.x, y = threadIdx.y;
    if (blockIdx.y < 63) {
        int f0 = blockIdx.x * 32;
        int h0 = blockIdx.y * 32;
        for (int i = y; i < 32; i += 8) {
            int h = h0 + i, f = f0 + x;
            tle[i][x] = (h < H4 && f < GG) ? W_ih[h * GG + f] : 0.f;
        }
        __syncthreads();
        for (int i = y; i < 32; i += 8) {
            int f = f0 + i, h = h0 + x;
            if (f < GG && h < H4) g_WihT[f * H4 + h] = tle[x][i];
        }
    } else {
        int k0 = blockIdx.x * 32;
        int r0 = (blockIdx.y - 63) * 32;
        for (int i = y; i < 32; i += 8) {
            int r = r0 + i, k = k0 + x;
            tle[i][x] = (r < H4 && k < HH) ? W_hh[r * HH + k] : 0.f;
        }
        __syncthreads();
        for (int i = y; i < 32; i += 8) {
            int k = k0 + i, r = r0 + x;
            if (k < HH && r < H4) {
                int g = r / HH, hc = r % HH;
                g_WXh[(size_t)(hc * 4 + g) * KP + k] = f2bf(tle[x][i]);
            }
        }
        if (blockIdx.x == 0 && blockIdx.y == 125) {
            int tid = y * 32 + x;
            for (int h = tid; h < H4; h += 256) {
                int q = (h % HH) * 4 + (h / HH);
                g_bias[q] = b_ih[h] + b_hh[h];
            }
        }
    }
}

// ------------------------- setup #3: tables + front(+seg) + zero init -------
__global__ void k_prep3(const float* __restrict__ x, const float* __restrict__ Ahat) {
    __shared__ float xr[LL], sp[LL], sn[LL];
    int blk = blockIdx.x;
    int tid = threadIdx.x;
    if (blk < 8) {
        int h = blk * 256 + tid;
        if (h < H4) {
            int q = (h % HH) * 4 + (h / HH);
            float accA = 0.f, accB = 0.f;
            for (int f = 0; f < GG; f++) {
                if (g_act0[f]) {
                    float w = g_WihT[f * H4 + h];
                    accA = fmaf(w, g_P[f],  accA);
                    accB = fmaf(w, g_Nv[f], accB);
                }
            }
            g_Aseg[q] = accA;
            g_Bseg[q] = accB;
            int E = g_nev[0];
            for (int e = 0; e < E; e++) {
                int f = g_ef[e];
                float sgn = g_esign[e];
                float w = g_WihT[f * H4 + h] * sgn;
                accA = fmaf(w, g_P[f],  accA);
                accB = fmaf(w, g_Nv[f], accB);
                g_Aseg[(e + 1) * H4P + q] = accA;
                g_Bseg[(e + 1) * H4P + q] = accB;
            }
        }
    } else {
        int bid = blk - 8;
        int b = bid / TT, t = bid % TT;
        if (tid < LL) xr[tid] = x[(b * TT + t) * LL + tid];
        __syncthreads();
        if (tid < LL) {
            float s = 0.f;
            const float* Ar = &Ahat[tid * LL];
            for (int l = 0; l < LL; l++) s = fmaf(Ar[l], xr[l], s);
            sp[tid] = fmaxf(s, 0.f);
            sn[tid] = fmaxf(-s, 0.f);
        }
        __syncthreads();
        if (tid < LL) {
            float uu = 0.f, vv = 0.f;
            const float* Ar = &Ahat[tid * LL];
            for (int l = 0; l < LL; l++) {
                uu = fmaf(Ar[l], sp[l], uu);
                vv = fmaf(Ar[l], sn[l], vv);
            }
            int n = b * LL + tid;
            int idx = t * NRP + n;
            g_u[idx] = uu;
            g_v[idx] = vv;
            int E = g_nev[0];
            int s;
            if (uu > 0.f) {
                float rho = vv / uu;
                int lo = 0, hi = E;
                while (lo < hi) {
                    int mid = (lo + hi) >> 1;
                    if (g_rho[mid] < rho) lo = mid + 1; else hi = mid;
                }
                s = lo;
            } else {
                s = (vv > 0.f) ? E : 0;
            }
            g_seg[idx] = s;
        }
    }
    // zero: h ring (u32), c, barrier counters, row-pad u/v/seg
    const int H3U = 3 * NRP * KP / 2;   // u32 words in g_h3
    const int CN  = HH * NRP;
    const int PADN = TT * (NRP - NR);
    const int ZT = H3U + CN + TT + PADN;
    int stride = gridDim.x * 256;
    for (int idx = blk * 256 + tid; idx < ZT; idx += stride) {
        if (idx < H3U) {
            reinterpret_cast<unsigned*>(g_h3)[idx] = 0u;
        } else if (idx < H3U + CN) {
            g_c[idx - H3U] = 0.f;
        } else if (idx < H3U + CN + TT) {
            g_bar[idx - H3U - CN] = 0u;
        } else {
            int i4 = idx - H3U - CN - TT;
            int t = i4 / (NRP - NR), r = NR + i4 % (NRP - NR);
            int p = t * NRP + r;
            g_u[p] = 0.f; g_v[p] = 0.f; g_seg[p] = 0;
        }
    }
}

// ------------------------- persistent LSTM (all 192 steps, one launch) ------
// 128 blocks = 32 col-tiles (64 gate-cols) x 4 row-tiles (128 rows). 256 thr.
// Warp = 16 cols x 64 rows (4 m-frags x 2 n-frags). W resident in smem.
__global__ __launch_bounds__(256) void k_lstm() {
    extern __shared__ __align__(16) char smc[];
    int tid  = threadIdx.x;
    int warp = tid >> 5;
    int lane = tid & 31;
    int g  = lane >> 2;
    int tg = lane & 3;
    int bx = blockIdx.x;
    int ct = bx & 31;        // col-tile
    int rt = bx >> 5;        // row-tile
    int cw = warp & 3;       // warp col group (16 cols)
    int rg = warp >> 2;      // warp row group (64 rows)
    int R0 = rt * ROWT;      // global row base
    int C0w = ct * COLT + cw * 16;   // warp's global gate-col base

    unsigned smbase = (unsigned)__cvta_generic_to_shared(smc);
    unsigned sWb = smbase;
    unsigned sAb = smbase + SWBYTES;

    // ---- load W stripe resident (once) ----
    for (int e = tid; e < COLT * 64; e += 256) {
        int col = e >> 6, q = e & 63;
        cp16(sWb + (unsigned)(col * WSTRC + q * 8) * 2,
             g_WXh + (size_t)(ct * COLT + col) * KP + q * 8);
    }
    cp_commit(); cp_wait<0>(); __syncthreads();

    // ---- ldmatrix lane address bases ----
    int arow  = (lane & 7) + ((lane >> 3) & 1) * 8;   // row within m16
    int akoff = ((lane >> 4) & 1) * 8;                // k half
    unsigned aBase[4];
    #pragma unroll
    for (int mi = 0; mi < 4; mi++)
        aBase[mi] = sAb + (unsigned)((rg * 64 + mi * 16 + arow) * ASTR + akoff) * 2;
    int wn    = cw * 16 + (lane & 7) + ((lane >> 4) & 1) * 8;
    int wkoff = ((lane >> 3) & 1) * 8;
    unsigned wBase = sWb + (unsigned)(wn * WSTRC + wkoff) * 2;

    for (int t = 0; t < TT; t++) {
        const unsigned short* hin = g_h3[(t + 2) % 3];   // h(t-1)
        unsigned short*      hout = g_h3[t % 3];         // h(t)

        // prefetch A slab 0
        {
            const unsigned short* src = hin + (size_t)R0 * KP;
            #pragma unroll 1
            for (int e = tid; e < ROWT * 16; e += 256) {
                int row = e >> 4, q = e & 15;
                cp16(sAb + (unsigned)(row * ASTR + q * 8) * 2,
                     src + (size_t)row * KP + q * 8);
            }
            cp_commit();
        }

        // prologue: d = u*Aseg[s] + v*Bseg[s] + bias (fp32 exact)
        float d[4][2][4];
        {
            int cA0 = C0w + 2 * tg;
            float2 bi0 = *(const float2*)&g_bias[cA0];
            float2 bi1 = *(const float2*)&g_bias[cA0 + 8];
            #pragma unroll
            for (int mi = 0; mi < 4; mi++) {
                int rA = R0 + rg * 64 + mi * 16 + g;
                int rB = rA + 8;
                int pA = t * NRP + rA, pB = t * NRP + rB;
                float uA = g_u[pA], vA = g_v[pA];
                float uB = g_u[pB], vB = g_v[pB];
                int sA = g_seg[pA], sB = g_seg[pB];
                #pragma unroll
                for (int ni = 0; ni < 2; ni++) {
                    int c = cA0 + ni * 8;
                    float2 bi = ni ? bi1 : bi0;
                    float2 aA = *(const float2*)&g_Aseg[sA * H4P + c];
                    float2 bA = *(const float2*)&g_Bseg[sA * H4P + c];
                    float2 aB = *(const float2*)&g_Aseg[sB * H4P + c];
                    float2 bB = *(const float2*)&g_Bseg[sB * H4P + c];
                    d[mi][ni][0] = fmaf(uA, aA.x, fmaf(vA, bA.x, bi.x));
                    d[mi][ni][1] = fmaf(uA, aA.y, fmaf(vA, bA.y, bi.y));
                    d[mi][ni][2] = fmaf(uB, aB.x, fmaf(vB, bB.x, bi.x));
                    d[mi][ni][3] = fmaf(uB, aB.y, fmaf(vB, bB.y, bi.y));
                }
            }
        }

        // main loop: 4 slabs of k=128, double-buffered
        #pragma unroll 1
        for (int s = 0; s < KP / SLABK; s++) {
            if (s + 1 < KP / SLABK) {
                const unsigned short* src = hin + (size_t)R0 * KP + (s + 1) * SLABK;
                unsigned dst = sAb + (unsigned)(((s + 1) & 1) * ABUF) * 2;
                #pragma unroll 1
                for (int e = tid; e < ROWT * 16; e += 256) {
                    int row = e >> 4, q = e & 15;
                    cp16(dst + (unsigned)(row * ASTR + q * 8) * 2,
                         src + (size_t)row * KP + q * 8);
                }
                cp_commit();
                cp_wait<1>();
            } else {
                cp_wait<0>();
            }
            __syncthreads();
            unsigned aOff = (unsigned)((s & 1) * ABUF) * 2;
            unsigned wOff = (unsigned)(s * SLABK) * 2;
            #pragma unroll
            for (int c16 = 0; c16 < SLABK / 16; c16++) {
                unsigned kb2 = (unsigned)(c16 * 16) * 2;
                unsigned a[4][4], b4[4];
                ldsm4(b4, wBase + wOff + kb2);
                #pragma unroll
                for (int mi = 0; mi < 4; mi++)
                    ldsm4(a[mi], aBase[mi] + aOff + kb2);
                #pragma unroll
                for (int mi = 0; mi < 4; mi++) {
                    mma16bf(d[mi][0], a[mi], b4);
                    mma16bf(d[mi][1], a[mi], b4 + 2);
                }
            }
            __syncthreads();
        }

        // epilogue: exchange gate pairs, even lanes do LSTM pointwise
        int last = (t == TT - 1);
        #pragma unroll
        for (int mi = 0; mi < 4; mi++) {
            #pragma unroll
            for (int ni = 0; ni < 2; ni++) {
                float d0 = d[mi][ni][0], d1 = d[mi][ni][1];
                float d2 = d[mi][ni][2], d3 = d[mi][ni][3];
                float e0 = __shfl_xor_sync(0xffffffffu, d0, 1);
                float e1 = __shfl_xor_sync(0xffffffffu, d1, 1);
                float e2 = __shfl_xor_sync(0xffffffffu, d2, 1);
                float e3 = __shfl_xor_sync(0xffffffffu, d3, 1);
                if ((lane & 1) == 0) {
                    int c0 = C0w + ni * 8 + 2 * tg;
                    int hc = c0 >> 2;
                    if (hc < HH) {
                        int rA = R0 + rg * 64 + mi * 16 + g;
                        int rB = rA + 8;
                        float cA = g_c[hc * NRP + rA];
                        float ig = fsig(d0), fg = fsig(d1), gg = ftanh(e0), og = fsig(e1);
                        float cn = fmaf(fg, cA, ig * gg);
                        g_c[hc * NRP + rA] = cn;
                        float hv = og * ftanh(cn);
                        hout[(size_t)rA * KP + hc] = f2bf(hv);
                        if (last) g_hF[hc * NRP + rA] = hv;
                        float cB = g_c[hc * NRP + rB];
                        ig = fsig(d2); fg = fsig(d3); gg = ftanh(e2); og = fsig(e3);
                        cn = fmaf(fg, cB, ig * gg);
                        g_c[hc * NRP + rB] = cn;
                        hv = og * ftanh(cn);
                        hout[(size_t)rB * KP + hc] = f2bf(hv);
                        if (last) g_hF[hc * NRP + rB] = hv;
                    }
                }
            }
        }

        // grid barrier
        __threadfence();
        __syncthreads();
        if (tid == 0) {
            atomicAdd(&g_bar[t], 1u);
            while (*(volatile unsigned*)&g_bar[t] < (unsigned)GRID7) {}
        }
        __syncthreads();
        __threadfence();
    }
}

// ------------------------- transpose h_last to row-major -------------------------
__global__ void k_trh() {
    int idx = blockIdx.x * 256 + threadIdx.x;
    if (idx >= NR * HH) return;
    int n = idx / HH, k = idx % HH;
    g_hT[idx] = g_hF[k * NRP + n];
}

// ------------------------- tf32 MMA GEMM: C = act(A @ W + b) ----------------
__device__ __forceinline__ float* selbuf(int s) {
    switch (s) {
        case 0: return g_hT;
        case 1: return g_z1;
        case 2: return g_z2;
        default: return g_z3;
    }
}

__global__ __launch_bounds__(256) void k_gemmt(int aSel, const float* __restrict__ W,
                                               const float* __restrict__ bias, int cSel,
                                               int M, int K, int N, int doRelu) {
    const float* A = selbuf(aSel);
    float* C = selbuf(cSel);
    __shared__ __align__(16) float As[64 * 36];
    __shared__ __align__(16) float Ws[32 * 72];
    int tid  = threadIdx.x;
    int warp = tid >> 5;
    int lane = tid & 31;
    int g  = lane >> 2;
    int tg = lane & 3;
    int n0 = blockIdx.x * 64, m0 = blockIdx.y * 64;
    int wm = (warp >> 2) * 32;
    int wn = (warp & 3) * 16;

    int ami = tid >> 2;
    int akq = (tid & 3) * 8;
    int wkk = tid >> 3;
    int wnq = (tid & 7) * 8;

    float d[2][2][4];
    #pragma unroll
    for (int i = 0; i < 2; i++)
        #pragma unroll
        for (int j = 0; j < 2; j++)
            #pragma unroll
            for (int q = 0; q < 4; q++) d[i][j][q] = 0.f;

    int nslab = (K + 31) / 32;
    float rA[8], rW[8];

    {
        int m = m0 + ami;
        #pragma unroll
        for (int j = 0; j < 8; j++) {
            int k = akq + j;
            rA[j] = (m < M && k < K) ? A[(size_t)m * K + k] : 0.f;
        }
        #pragma unroll
        for (int j = 0; j < 8; j++) {
            int n = n0 + wnq + j;
            rW[j] = (wkk < K && n < N) ? W[(size_t)wkk * N + n] : 0.f;
        }
    }

    #pragma unroll 1
    for (int s = 0; s < nslab; s++) {
        #pragma unroll
        for (int j = 0; j < 8; j++) As[ami * 36 + akq + j] = tf32r(rA[j]);
        #pragma unroll
        for (int j = 0; j < 8; j++) Ws[wkk * 72 + wnq + j] = tf32r(rW[j]);
        __syncthreads();
        if (s + 1 < nslab) {
            int k0 = (s + 1) * 32;
            int m = m0 + ami;
            #pragma unroll
            for (int j = 0; j < 8; j++) {
                int k = k0 + akq + j;
                rA[j] = (m < M && k < K) ? A[(size_t)m * K + k] : 0.f;
            }
            #pragma unroll
            for (int j = 0; j < 8; j++) {
                int k = k0 + wkk;
                int n = n0 + wnq + j;
                rW[j] = (k < K && n < N) ? W[(size_t)k * N + n] : 0.f;
            }
        }
        const unsigned* Asu = reinterpret_cast<const unsigned*>(As);
        const unsigned* Wsu = reinterpret_cast<const unsigned*>(Ws);
        #pragma unroll
        for (int c8 = 0; c8 < 4; c8++) {
            int kc = c8 * 8;
            unsigned a[2][4], b[2][2];
            #pragma unroll
            for (int mi = 0; mi < 2; mi++) {
                int mbase = (wm + mi * 16 + g) * 36 + kc;
                a[mi][0] = Asu[mbase + tg];
                a[mi][1] = Asu[mbase + 8 * 36 + tg];
                a[mi][2] = Asu[mbase + tg + 4];
                a[mi][3] = Asu[mbase + 8 * 36 + tg + 4];
            }
            #pragma unroll
            for (int ni = 0; ni < 2; ni++) {
                int nb = wn + ni * 8 + g;
                b[ni][0] = Wsu[(kc + tg) * 72 + nb];
                b[ni][1] = Wsu[(kc + tg + 4) * 72 + nb];
            }
            #pragma unroll
            for (int mi = 0; mi < 2; mi++)
                #pragma unroll
                for (int ni = 0; ni < 2; ni++)
                    mma8(d[mi][ni], a[mi], b[ni]);
        }
        __syncthreads();
    }

    #pragma unroll
    for (int mi = 0; mi < 2; mi++) {
        #pragma unroll
        for (int ni = 0; ni < 2; ni++) {
            int mA = m0 + wm + mi * 16 + g;
            int mB = mA + 8;
            int n  = n0 + wn + ni * 8 + 2 * tg;
            float b0 = (n < N)     ? bias[n]     : 0.f;
            float b1 = (n + 1 < N) ? bias[n + 1] : 0.f;
            float v;
            if (mA < M) {
                if (n < N) {
                    v = d[mi][ni][0] + b0;
                    C[(size_t)mA * N + n] = doRelu ? fmaxf(v, 0.f) : v;
                }
                if (n + 1 < N) {
                    v = d[mi][ni][1] + b1;
                    C[(size_t)mA * N + n + 1] = doRelu ? fmaxf(v, 0.f) : v;
                }
            }
            if (mB < M) {
                if (n < N) {
                    v = d[mi][ni][2] + b0;
                    C[(size_t)mB * N + n] = doRelu ? fmaxf(v, 0.f) : v;
                }
                if (n + 1 < N) {
                    v = d[mi][ni][3] + b1;
                    C[(size_t)mB * N + n + 1] = doRelu ? fmaxf(v, 0.f) : v;
                }
            }
        }
    }
}

// ------------------------- final layer -------------------------
__global__ void k_final(const float* __restrict__ Wh4, const float* __restrict__ bh4,
                        float* __restrict__ out) {
    __shared__ float zs[M1];
    int n = blockIdx.x;
    int tid = threadIdx.x;
    for (int k = tid; k < M1; k += 256) zs[k] = g_z3[n * M1 + k];
    __syncthreads();
    int w = tid >> 5, lane = tid & 31;
    #pragma unroll
    for (int oi = 0; oi < 3; oi++) {
        int o = w + oi * 8;
        float p = 0.f;
        for (int k = lane; k < M1; k += 32) p = fmaf(zs[k], Wh4[k * OD + o], p);
        #pragma unroll
        for (int off = 16; off; off >>= 1) p += __shfl_down_sync(0xffffffffu, p, off);
        if (lane == 0) {
            float y = fsig(p + bh4[o]);
            int b = n / LL, l = n % LL;
            out[(b * OD + o) * LL + l] = y;
        }
    }
}

// ------------------------- launcher -------------------------
extern "C" void kernel_launch(void* const* d_in, const int* in_sizes, int n_in,
                              void* d_out, int out_size) {
    const float* x    = (const float*)d_in[0];
    const float* Ahat = (const float*)d_in[1];
    const float* W1   = (const float*)d_in[2];
    const float* W2   = (const float*)d_in[3];
    const float* W_ih = (const float*)d_in[4];
    const float* W_hh = (const float*)d_in[5];
    const float* b_ih = (const float*)d_in[6];
    const float* b_hh = (const float*)d_in[7];
    const float* Wh1  = (const float*)d_in[8];
    const float* bh1  = (const float*)d_in[9];
    const float* Wh2  = (const float*)d_in[10];
    const float* bh2  = (const float*)d_in[11];
    const float* Wh3  = (const float*)d_in[12];
    const float* bh3  = (const float*)d_in[13];
    const float* Wh4  = (const float*)d_in[14];
    const float* bh4  = (const float*)d_in[15];
    float* out = (float*)d_out;

    cudaFuncSetAttribute(k_lstm, cudaFuncAttributeMaxDynamicSharedMemorySize, SMEM7);

    k_setup1<<<1, 512>>>(W1, W2);
    k_trans<<<dim3(16, 126), dim3(32, 8)>>>(W_ih, W_hh, b_ih, b_hh);
    k_prep3<<<8 + BB * TT, 256>>>(x, Ahat);

    // one persistent launch runs all 192 LSTM steps
    k_lstm<<<GRID7, 256, SMEM7>>>();

    k_trh<<<(NR * HH + 255) / 256, 256>>>();

    k_gemmt<<<dim3(47, 8), 256>>>(0, Wh1, bh1, 1, NR, HH, M1, 1);
    k_gemmt<<<dim3(16, 8), 256>>>(1, Wh2, bh2, 2, NR, M1, M2, 1);
    k_gemmt<<<dim3(47, 8), 256>>>(2, Wh3, bh3, 3, NR, M2, M1, 1);
    k_final<<<NR, 256>>>(Wh4, bh4, out);
}